// round 12
// baseline (speedup 1.0000x reference)
#include <cuda_runtime.h>
#include <cuda_bf16.h>
#include <math.h>
#include <stdint.h>

#define Bv 2
#define Tv 2048
#define Dv 1024
#define Hv 16
#define HDv 64
#define Mv 4096          // B*T
#define Kv 1024
#define QKV_N 3072

// ---------------- device scratch (no allocations allowed) ------------------
__device__ __align__(16) __nv_bfloat16 g_Qh[Bv*Hv*Tv*HDv], g_Ql[Bv*Hv*Tv*HDv];
__device__ __align__(16) __nv_bfloat16 g_Kh[Bv*Hv*Tv*HDv], g_Kl[Bv*Hv*Tv*HDv];
__device__ __align__(16) __nv_bfloat16 g_Vh[Bv*Hv*Tv*HDv], g_Vl[Bv*Hv*Tv*HDv];

__device__ __align__(16) __nv_bfloat16 g_xh[Mv*Kv],     g_xl[Mv*Kv];
__device__ __align__(16) __nv_bfloat16 g_wqh[QKV_N*Kv], g_wql[QKV_N*Kv];
__device__ __align__(16) __nv_bfloat16 g_ah[Mv*Kv],     g_al[Mv*Kv];   // attn out hi/lo
__device__ __align__(16) __nv_bfloat16 g_woh[Dv*Kv],    g_wol[Dv*Kv];

// ---------------- PTX helpers ------------------------------------------------
__device__ __forceinline__ uint32_t smem_u32(const void* p) {
    uint32_t a;
    asm("{ .reg .u64 t; cvta.to.shared.u64 t, %1; cvt.u32.u64 %0, t; }" : "=r"(a) : "l"(p));
    return a;
}
__device__ __forceinline__ void cp16(uint32_t s, const void* g) {
    asm volatile("cp.async.cg.shared.global [%0], [%1], 16;" :: "r"(s), "l"(g));
}
#define CP_COMMIT()  asm volatile("cp.async.commit_group;" ::: "memory")
#define CP_WAIT_0()  asm volatile("cp.async.wait_group 0;" ::: "memory")

__device__ __forceinline__ void ldm_x4(uint32_t* r, uint32_t a) {
    asm volatile("ldmatrix.sync.aligned.m8n8.x4.shared.b16 {%0,%1,%2,%3}, [%4];"
        : "=r"(r[0]), "=r"(r[1]), "=r"(r[2]), "=r"(r[3]) : "r"(a));
}
__device__ __forceinline__ void ldm_x4_t(uint32_t* r, uint32_t a) {
    asm volatile("ldmatrix.sync.aligned.m8n8.x4.trans.shared.b16 {%0,%1,%2,%3}, [%4];"
        : "=r"(r[0]), "=r"(r[1]), "=r"(r[2]), "=r"(r[3]) : "r"(a));
}
__device__ __forceinline__ void mma_bf16(float* d, const uint32_t* a,
                                         uint32_t b0, uint32_t b1) {
    asm volatile(
        "mma.sync.aligned.m16n8k16.row.col.f32.bf16.bf16.f32 "
        "{%0,%1,%2,%3}, {%4,%5,%6,%7}, {%8,%9}, {%0,%1,%2,%3};"
        : "+f"(d[0]), "+f"(d[1]), "+f"(d[2]), "+f"(d[3])
        : "r"(a[0]), "r"(a[1]), "r"(a[2]), "r"(a[3]), "r"(b0), "r"(b1));
}
__device__ __forceinline__ void pack_hl(float p0, float p1, uint32_t& h, uint32_t& l) {
    __nv_bfloat16 b0 = __float2bfloat16(p0), b1 = __float2bfloat16(p1);
    h = (uint32_t)__bfloat16_as_ushort(b0) | ((uint32_t)__bfloat16_as_ushort(b1) << 16);
    __nv_bfloat16 r0 = __float2bfloat16(p0 - __bfloat162float(b0));
    __nv_bfloat16 r1 = __float2bfloat16(p1 - __bfloat162float(b1));
    l = (uint32_t)__bfloat16_as_ushort(r0) | ((uint32_t)__bfloat16_as_ushort(r1) << 16);
}

// ---------------- fused split fp32 -> (hi, lo) bf16 (all 3 tensors) ---------
#define XN4   (Mv * Kv / 4)         // 1,048,576
#define WQN4  (QKV_N * Kv / 4)      //   786,432
#define WON4  (Dv * Kv / 4)         //   262,144

__global__ __launch_bounds__(256) void split_all_kernel(const float* __restrict__ x,
                                                        const float* __restrict__ wq,
                                                        const float* __restrict__ wo,
                                                        __nv_bfloat16* __restrict__ xh,
                                                        __nv_bfloat16* __restrict__ xl,
                                                        __nv_bfloat16* __restrict__ wqh,
                                                        __nv_bfloat16* __restrict__ wql,
                                                        __nv_bfloat16* __restrict__ woh,
                                                        __nv_bfloat16* __restrict__ wol) {
    int i = blockIdx.x * blockDim.x + threadIdx.x;
    const float* s; __nv_bfloat16 *hi, *lo;
    if (i < XN4)                 { s = x;  hi = xh;  lo = xl; }
    else if (i < XN4 + WQN4)     { i -= XN4;        s = wq; hi = wqh; lo = wql; }
    else if (i < XN4+WQN4+WON4)  { i -= XN4 + WQN4; s = wo; hi = woh; lo = wol; }
    else return;
    float4 v = reinterpret_cast<const float4*>(s)[i];
    ushort4 h, l;
    __nv_bfloat16 b;
    b = __float2bfloat16(v.x); h.x = __bfloat16_as_ushort(b);
    l.x = __bfloat16_as_ushort(__float2bfloat16(v.x - __bfloat162float(b)));
    b = __float2bfloat16(v.y); h.y = __bfloat16_as_ushort(b);
    l.y = __bfloat16_as_ushort(__float2bfloat16(v.y - __bfloat162float(b)));
    b = __float2bfloat16(v.z); h.z = __bfloat16_as_ushort(b);
    l.z = __bfloat16_as_ushort(__float2bfloat16(v.z - __bfloat162float(b)));
    b = __float2bfloat16(v.w); h.w = __bfloat16_as_ushort(b);
    l.w = __bfloat16_as_ushort(__float2bfloat16(v.w - __bfloat162float(b)));
    reinterpret_cast<ushort4*>(hi)[i] = h;
    reinterpret_cast<ushort4*>(lo)[i] = l;
}

// ---------------- HMMA GEMM v2: 128x64 CTA tile, 3 CTAs/SM (R11) ------------
#define RS      40
#define TILE_A  (128 * RS * 2)
#define TILE_Bt (64  * RS * 2)
#define STG_B   (2 * TILE_A + 2 * TILE_Bt)

#define DO_KSTEP(KO) \
    { \
        uint32_t ah[2][4], bh[2][4]; \
        _Pragma("unroll") \
        for (int i = 0; i < 2; i++) \
            ldm_x4(ah[i], a_base + s + (KO) + (uint32_t)i * (16 * RS * 2)); \
        _Pragma("unroll") \
        for (int j = 0; j < 2; j++) \
            ldm_x4(bh[j], b_base + s + (KO) + (uint32_t)j * (16 * RS * 2)); \
        _Pragma("unroll") \
        for (int i = 0; i < 2; i++) \
            _Pragma("unroll") \
            for (int n = 0; n < 4; n++) \
                mma_bf16(acc[i][n], ah[i], bh[n>>1][n&1], bh[n>>1][2+(n&1)]); \
        uint32_t bl[2][4]; \
        _Pragma("unroll") \
        for (int j = 0; j < 2; j++) \
            ldm_x4(bl[j], b_base + s + (KO) + TILE_Bt + (uint32_t)j * (16 * RS * 2)); \
        _Pragma("unroll") \
        for (int i = 0; i < 2; i++) \
            _Pragma("unroll") \
            for (int n = 0; n < 4; n++) \
                mma_bf16(acc[i][n], ah[i], bl[n>>1][n&1], bl[n>>1][2+(n&1)]); \
        uint32_t al[2][4]; \
        _Pragma("unroll") \
        for (int i = 0; i < 2; i++) \
            ldm_x4(al[i], a_base + s + (KO) + TILE_A + (uint32_t)i * (16 * RS * 2)); \
        _Pragma("unroll") \
        for (int i = 0; i < 2; i++) \
            _Pragma("unroll") \
            for (int n = 0; n < 4; n++) \
                mma_bf16(acc[i][n], al[i], bh[n>>1][n&1], bh[n>>1][2+(n&1)]); \
    }

#define DO_PREFETCH() \
    if (kt + 1 < NCHUNK) { \
        const uint32_t s1 = (uint32_t)((kt + 1) & 1) * STG_B; \
        const int k1 = (kt + 1) * 32; \
        _Pragma("unroll") \
        for (int i = 0; i < 2; i++) { \
            cp16(dsb + s1 + soffA[i],           Ahb + goffA[i] + k1); \
            cp16(dsb + s1 + TILE_A + soffA[i],  Alb + goffA[i] + k1); \
        } \
        cp16(dsb + s1 + 2u*TILE_A + soffB,           Bhb + goffB + k1); \
        cp16(dsb + s1 + 2u*TILE_A + TILE_Bt + soffB, Blb + goffB + k1); \
        CP_COMMIT(); \
    }

__global__ __launch_bounds__(256, 3) void gemm_mma(const __nv_bfloat16* __restrict__ Ah,
                                                   const __nv_bfloat16* __restrict__ Al,
                                                   const __nv_bfloat16* __restrict__ Bh,
                                                   const __nv_bfloat16* __restrict__ Bl,
                                                   const float* __restrict__ bias,
                                                   float* __restrict__ C, int MODE) {
    extern __shared__ __align__(1024) char dsm[];
    const uint32_t dsb = smem_u32(dsm);

    const int t    = threadIdx.x;
    const int lane = t & 31;
    const int wid  = t >> 5;
    const int wm   = wid & 3;
    const int wn   = wid >> 2;
    const int m0   = blockIdx.y * 128;
    const int n0   = blockIdx.x * 64;

    int goffA[2]; uint32_t soffA[2];
    #pragma unroll
    for (int i = 0; i < 2; i++) {
        int g   = t + i * 256;
        int row = g >> 2;
        int c8  = (g & 3) * 8;
        goffA[i] = row * Kv + c8;
        soffA[i] = (uint32_t)(row * RS + c8) * 2;
    }
    const int      goffB = (t >> 2) * Kv + (t & 3) * 8;
    const uint32_t soffB = (uint32_t)((t >> 2) * RS + (t & 3) * 8) * 2;

    const __nv_bfloat16* Ahb = Ah + (size_t)m0 * Kv;
    const __nv_bfloat16* Alb = Al + (size_t)m0 * Kv;
    const __nv_bfloat16* Bhb = Bh + (size_t)n0 * Kv;
    const __nv_bfloat16* Blb = Bl + (size_t)n0 * Kv;

    const uint32_t a_base = dsb + (uint32_t)((wm * 32 + (lane & 15)) * RS + (lane >> 4) * 8) * 2;
    const uint32_t b_base = dsb + 2u * TILE_A
                          + (uint32_t)((wn * 32 + (lane & 15)) * RS + (lane >> 4) * 8) * 2;

    float acc[2][4][4];
    #pragma unroll
    for (int i = 0; i < 2; i++)
        #pragma unroll
        for (int n = 0; n < 4; n++)
            #pragma unroll
            for (int r = 0; r < 4; r++) acc[i][n][r] = 0.0f;

    #pragma unroll
    for (int i = 0; i < 2; i++) {
        cp16(dsb + soffA[i],          Ahb + goffA[i]);
        cp16(dsb + TILE_A + soffA[i], Alb + goffA[i]);
    }
    cp16(dsb + 2u*TILE_A + soffB,           Bhb + goffB);
    cp16(dsb + 2u*TILE_A + TILE_Bt + soffB, Blb + goffB);
    CP_COMMIT();

    const int NCHUNK = Kv / 32;
    for (int kt = 0; kt < NCHUNK; kt++) {
        const uint32_t s = (uint32_t)(kt & 1) * STG_B;
        CP_WAIT_0();
        __syncthreads();

        if (wid & 1) {
            DO_KSTEP(32)
            DO_PREFETCH()
            DO_KSTEP(0)
        } else {
            DO_KSTEP(0)
            DO_PREFETCH()
            DO_KSTEP(32)
        }
    }

    if (MODE == 0) {
        #pragma unroll
        for (int i = 0; i < 2; i++)
            #pragma unroll
            for (int n = 0; n < 4; n++)
                #pragma unroll
                for (int r = 0; r < 4; r++) {
                    int row = m0 + wm * 32 + i * 16 + (lane >> 2) + (r >> 1) * 8;
                    int col = n0 + wn * 32 + n * 8 + (lane & 3) * 2 + (r & 1);
                    float v = acc[i][n][r] + __ldg(bias + col);
                    int bb = row >> 11;
                    int tt = row & (Tv - 1);
                    int h  = col / 192;
                    int rr = col - h * 192;
                    size_t off = (((size_t)(bb * Hv + h)) * Tv + tt) * HDv + (rr & 63);
                    __nv_bfloat16 hi = __float2bfloat16(v);
                    __nv_bfloat16 lo = __float2bfloat16(v - __bfloat162float(hi));
                    if (rr < 64)       { g_Qh[off] = hi; g_Ql[off] = lo; }
                    else if (rr < 128) { g_Kh[off] = hi; g_Kl[off] = lo; }
                    else               { g_Vh[off] = hi; g_Vl[off] = lo; }
                }
    } else {
        #pragma unroll
        for (int i = 0; i < 2; i++)
            #pragma unroll
            for (int n = 0; n < 4; n++) {
                int row = m0 + wm * 32 + i * 16 + (lane >> 2);
                int col = n0 + wn * 32 + n * 8 + (lane & 3) * 2;
                float b0 = __ldg(bias + col), b1 = __ldg(bias + col + 1);
                float2 v0 = make_float2(acc[i][n][0] + b0, acc[i][n][1] + b1);
                float2 v1 = make_float2(acc[i][n][2] + b0, acc[i][n][3] + b1);
                *reinterpret_cast<float2*>(C + (size_t)row * Dv + col)       = v0;
                *reinterpret_cast<float2*>(C + (size_t)(row + 8) * Dv + col) = v1;
            }
    }
}

// ---------------- flash attention: 512 threads, 256-query tile --------------
#define FRS        72
#define FQROWS     256
#define FQ_TILE_B  (FQROWS * FRS * 2)       // 36864
#define FK_TILE_B  (64 * FRS * 2)           // 9216
#define FST_B      (4 * FK_TILE_B)          // 36864
#define FLASH_SMEM (2 * FQ_TILE_B + 2 * FST_B)  // 147456

__global__ __launch_bounds__(512, 1) void flash_mma() {
    extern __shared__ __align__(1024) char fsm[];
    const uint32_t base = smem_u32(fsm);

    const int t    = threadIdx.x;
    const int lane = t & 31;
    const int wid  = t >> 5;                 // 0..15
    const int bh   = blockIdx.y;
    const int qt   = (Tv / FQROWS - 1) - blockIdx.x;   // big tiles first
    const int q0   = qt * FQROWS;
    const int NKT  = 4 * qt + 4;

    const __nv_bfloat16* Qhg = g_Qh + ((size_t)bh * Tv + q0) * HDv;
    const __nv_bfloat16* Qlg = g_Ql + ((size_t)bh * Tv + q0) * HDv;
    const __nv_bfloat16* Khg = g_Kh + (size_t)bh * Tv * HDv;
    const __nv_bfloat16* Klg = g_Kl + (size_t)bh * Tv * HDv;
    const __nv_bfloat16* Vhg = g_Vh + (size_t)bh * Tv * HDv;
    const __nv_bfloat16* Vlg = g_Vl + (size_t)bh * Tv * HDv;

    // ---- Q tile load (256 rows x 64 cols, hi+lo) ----
    #pragma unroll
    for (int i = 0; i < 4; i++) {
        int g = t + i * 512;                 // 0..2047
        int r = g >> 3;
        int c8 = (g & 7) * 8;
        uint32_t so = (uint32_t)(r * FRS + c8) * 2;
        cp16(base + so,             Qhg + r * HDv + c8);
        cp16(base + FQ_TILE_B + so, Qlg + r * HDv + c8);
    }
    CP_COMMIT();
    // ---- stage 0 KV ----
    {
        int r = t >> 3, c8 = (t & 7) * 8;
        uint32_t st = base + 2 * FQ_TILE_B;
        uint32_t so = (uint32_t)(r * FRS + c8) * 2;
        int go = r * HDv + c8;
        cp16(st + so,               Khg + go);
        cp16(st + FK_TILE_B + so,   Klg + go);
        cp16(st + 2*FK_TILE_B + so, Vhg + go);
        cp16(st + 3*FK_TILE_B + so, Vlg + go);
    }
    CP_COMMIT();

    const int qw0 = q0 + wid * 16;
    float m_[2] = {-INFINITY, -INFINITY};
    float l_[2] = {0.0f, 0.0f};
    float o[8][4];
    #pragma unroll
    for (int n = 0; n < 8; n++)
        #pragma unroll
        for (int e = 0; e < 4; e++) o[n][e] = 0.0f;

    const uint32_t q_lmb  = base + (uint32_t)((wid * 16 + (lane & 15)) * FRS + (lane >> 4) * 8) * 2;
    const uint32_t k_lane = (uint32_t)((lane & 15) * FRS + (lane >> 4) * 8) * 2;
    const uint32_t v_lane = (uint32_t)(((lane & 7) + ((lane >> 4) << 3)) * FRS + ((lane >> 3) & 1) * 8) * 2;

    for (int kt = 0; kt < NKT; kt++) {
        const uint32_t st = base + 2 * FQ_TILE_B + (uint32_t)(kt & 1) * FST_B;
        CP_WAIT_0();
        __syncthreads();   // single barrier per tile
        if (kt + 1 < NKT) {
            const uint32_t st1 = base + 2 * FQ_TILE_B + (uint32_t)((kt + 1) & 1) * FST_B;
            const int kr = (kt + 1) * 64;
            int r = t >> 3, c8 = (t & 7) * 8;
            uint32_t so = (uint32_t)(r * FRS + c8) * 2;
            int go = (kr + r) * HDv + c8;
            cp16(st1 + so,               Khg + go);
            cp16(st1 + FK_TILE_B + so,   Klg + go);
            cp16(st1 + 2*FK_TILE_B + so, Vhg + go);
            cp16(st1 + 3*FK_TILE_B + so, Vlg + go);
            CP_COMMIT();
        }

        const int k0 = kt * 64;
        if (k0 <= qw0 + 15) {
            // ---- S = Q K^T (split, pass-major; Q fragments reloaded) ----
            float sa[8][4];
            #pragma unroll
            for (int n = 0; n < 8; n++)
                #pragma unroll
                for (int e = 0; e < 4; e++) sa[n][e] = 0.0f;

            #pragma unroll
            for (int kg = 0; kg < 4; kg++) {
                uint32_t qhf[4], qlf[4];
                ldm_x4(qhf, q_lmb + kg * 32);
                ldm_x4(qlf, q_lmb + FQ_TILE_B + kg * 32);
                uint32_t kb[4][4], kl[4][4];
                #pragma unroll
                for (int np = 0; np < 4; np++) {
                    uint32_t addr = st + k_lane + (uint32_t)(np * 16 * FRS * 2) + kg * 32;
                    ldm_x4(kb[np], addr);
                    ldm_x4(kl[np], addr + FK_TILE_B);
                }
                #pragma unroll
                for (int np = 0; np < 4; np++) {
                    mma_bf16(sa[2*np],   qhf, kb[np][0], kb[np][2]);
                    mma_bf16(sa[2*np+1], qhf, kb[np][1], kb[np][3]);
                }
                #pragma unroll
                for (int np = 0; np < 4; np++) {
                    mma_bf16(sa[2*np],   qhf, kl[np][0], kl[np][2]);
                    mma_bf16(sa[2*np+1], qhf, kl[np][1], kl[np][3]);
                }
                #pragma unroll
                for (int np = 0; np < 4; np++) {
                    mma_bf16(sa[2*np],   qlf, kb[np][0], kb[np][2]);
                    mma_bf16(sa[2*np+1], qlf, kb[np][1], kb[np][3]);
                }
            }

            // ---- scale + causal mask ----
            const int r0 = qw0 + (lane >> 2);
            #pragma unroll
            for (int n = 0; n < 8; n++)
                #pragma unroll
                for (int e = 0; e < 4; e++) {
                    float v = sa[n][e] * 0.125f;
                    int rr = r0 + (e >> 1) * 8;
                    int cc = k0 + n * 8 + (lane & 3) * 2 + (e & 1);
                    sa[n][e] = (cc > rr) ? -INFINITY : v;
                }

            // ---- online softmax ----
            float corr[2];
            #pragma unroll
            for (int rh = 0; rh < 2; rh++) {
                float mx = -INFINITY;
                #pragma unroll
                for (int n = 0; n < 8; n++)
                    mx = fmaxf(mx, fmaxf(sa[n][2*rh], sa[n][2*rh+1]));
                mx = fmaxf(mx, __shfl_xor_sync(0xffffffffu, mx, 1));
                mx = fmaxf(mx, __shfl_xor_sync(0xffffffffu, mx, 2));
                float mnew = fmaxf(m_[rh], mx);
                corr[rh] = __expf(m_[rh] - mnew);
                m_[rh] = mnew;
                float rs = 0.0f;
                #pragma unroll
                for (int n = 0; n < 8; n++) {
                    float p0 = __expf(sa[n][2*rh]   - mnew);
                    float p1 = __expf(sa[n][2*rh+1] - mnew);
                    sa[n][2*rh] = p0; sa[n][2*rh+1] = p1;
                    rs += p0 + p1;
                }
                rs += __shfl_xor_sync(0xffffffffu, rs, 1);
                rs += __shfl_xor_sync(0xffffffffu, rs, 2);
                l_[rh] = l_[rh] * corr[rh] + rs;
            }
            #pragma unroll
            for (int n = 0; n < 8; n++) {
                o[n][0] *= corr[0]; o[n][1] *= corr[0];
                o[n][2] *= corr[1]; o[n][3] *= corr[1];
            }

            // ---- O += P V (split, pass-major) ----
            #pragma unroll
            for (int kg = 0; kg < 4; kg++) {
                uint32_t pah[4], pal[4];
                pack_hl(sa[2*kg][0],   sa[2*kg][1],   pah[0], pal[0]);
                pack_hl(sa[2*kg][2],   sa[2*kg][3],   pah[1], pal[1]);
                pack_hl(sa[2*kg+1][0], sa[2*kg+1][1], pah[2], pal[2]);
                pack_hl(sa[2*kg+1][2], sa[2*kg+1][3], pah[3], pal[3]);
                uint32_t vb[4][4], vl[4][4];
                #pragma unroll
                for (int ndp = 0; ndp < 4; ndp++) {
                    uint32_t addr = st + 2*FK_TILE_B + v_lane
                                  + (uint32_t)(kg * 16 * FRS * 2) + ndp * 32;
                    ldm_x4_t(vb[ndp], addr);
                    ldm_x4_t(vl[ndp], addr + FK_TILE_B);
                }
                #pragma unroll
                for (int ndp = 0; ndp < 4; ndp++) {
                    mma_bf16(o[2*ndp],   pah, vb[ndp][0], vb[ndp][2]);
                    mma_bf16(o[2*ndp+1], pah, vb[ndp][1], vb[ndp][3]);
                }
                #pragma unroll
                for (int ndp = 0; ndp < 4; ndp++) {
                    mma_bf16(o[2*ndp],   pah, vl[ndp][0], vl[ndp][2]);
                    mma_bf16(o[2*ndp+1], pah, vl[ndp][1], vl[ndp][3]);
                }
                #pragma unroll
                for (int ndp = 0; ndp < 4; ndp++) {
                    mma_bf16(o[2*ndp],   pal, vb[ndp][0], vb[ndp][2]);
                    mma_bf16(o[2*ndp+1], pal, vb[ndp][1], vb[ndp][3]);
                }
            }
        }
    }

    // ---- finalize: write bf16 hi/lo attention output directly --------------
    const int bb = bh >> 4;
    const int h  = bh & 15;
    const float i0 = 1.0f / l_[0], i1 = 1.0f / l_[1];
    const int row = q0 + wid * 16 + (lane >> 2);
    const size_t base0 = ((size_t)(bb * Tv) + row) * Dv;
    const size_t base1 = base0 + (size_t)8 * Dv;
    #pragma unroll
    for (int nd = 0; nd < 8; nd++) {
        int col = h * 64 + nd * 8 + (lane & 3) * 2;
        uint32_t h0, l0, h1, l1;
        pack_hl(o[nd][0] * i0, o[nd][1] * i0, h0, l0);
        pack_hl(o[nd][2] * i1, o[nd][3] * i1, h1, l1);
        *reinterpret_cast<uint32_t*>(&g_ah[base0 + col]) = h0;
        *reinterpret_cast<uint32_t*>(&g_al[base0 + col]) = l0;
        *reinterpret_cast<uint32_t*>(&g_ah[base1 + col]) = h1;
        *reinterpret_cast<uint32_t*>(&g_al[base1 + col]) = l1;
    }
}

// ---------------------------------------------------------------------------
extern "C" void kernel_launch(void* const* d_in, const int* in_sizes, int n_in,
                              void* d_out, int out_size) {
    const float* x    = (const float*)d_in[0];
    const float* Wqkv = (const float*)d_in[1];
    const float* bqkv = (const float*)d_in[2];
    const float* Wout = (const float*)d_in[3];
    const float* bout = (const float*)d_in[4];
    float* out = (float*)d_out;

    void *xh, *xl, *wqh, *wql, *ah, *al, *woh, *wol;
    cudaGetSymbolAddress(&xh,  g_xh);  cudaGetSymbolAddress(&xl,  g_xl);
    cudaGetSymbolAddress(&wqh, g_wqh); cudaGetSymbolAddress(&wql, g_wql);
    cudaGetSymbolAddress(&ah,  g_ah);  cudaGetSymbolAddress(&al,  g_al);
    cudaGetSymbolAddress(&woh, g_woh); cudaGetSymbolAddress(&wol, g_wol);

    cudaFuncSetAttribute(gemm_mma,  cudaFuncAttributeMaxDynamicSharedMemorySize, 2 * STG_B);
    cudaFuncSetAttribute(flash_mma, cudaFuncAttributeMaxDynamicSharedMemorySize, FLASH_SMEM);

    // fused fp32 -> (hi,lo) bf16 splits (x, Wqkv, Wout)
    split_all_kernel<<<(XN4 + WQN4 + WON4 + 255) / 256, 256>>>(
        x, Wqkv, Wout,
        (__nv_bfloat16*)xh,  (__nv_bfloat16*)xl,
        (__nv_bfloat16*)wqh, (__nv_bfloat16*)wql,
        (__nv_bfloat16*)woh, (__nv_bfloat16*)wol);

    // 1) QKV projection -> bf16 hi/lo Q,K,V   (CTA tile 128x64)
    gemm_mma<<<dim3(QKV_N / 64, Mv / 128), 256, 2 * STG_B>>>(
        (__nv_bfloat16*)xh, (__nv_bfloat16*)xl, (__nv_bfloat16*)wqh, (__nv_bfloat16*)wql,
        bqkv, nullptr, 0);

    // 2) causal flash attention -> bf16 hi/lo attention output
    flash_mma<<<dim3(Tv / FQROWS, Bv * Hv), 512, FLASH_SMEM>>>();

    // 3) output projection
    gemm_mma<<<dim3(Dv / 64, Mv / 128), 256, 2 * STG_B>>>(
        (__nv_bfloat16*)ah, (__nv_bfloat16*)al, (__nv_bfloat16*)woh, (__nv_bfloat16*)wol,
        bout, out, 1);
}

// round 13
// speedup vs baseline: 1.2504x; 1.2504x over previous
#include <cuda_runtime.h>
#include <cuda_bf16.h>
#include <cuda_fp16.h>
#include <math.h>
#include <stdint.h>

#define Bv 2
#define Tv 2048
#define Dv 1024
#define Hv 16
#define HDv 64
#define Mv 4096          // B*T
#define Kv 1024
#define QKV_N 3072

// ---------------- device scratch (no allocations allowed) ------------------
__device__ __align__(16) __half g_Qh[Bv*Hv*Tv*HDv], g_Ql[Bv*Hv*Tv*HDv];  // fp16 pair
__device__ __align__(16) __half g_Kh[Bv*Hv*Tv*HDv];                       // fp16 single
__device__ __align__(16) __half g_Vh[Bv*Hv*Tv*HDv];                       // fp16 single

__device__ __align__(16) __nv_bfloat16 g_xh[Mv*Kv],     g_xl[Mv*Kv];      // bf16 pair
__device__ __align__(16) __nv_bfloat16 g_wqh[QKV_N*Kv], g_wql[QKV_N*Kv];  // bf16 pair
__device__ __align__(16) __half g_ah[Mv*Kv], g_al[Mv*Kv];                 // fp16 pair
__device__ __align__(16) __half g_woh[Dv*Kv];                             // fp16 single

// ---------------- PTX helpers ------------------------------------------------
__device__ __forceinline__ uint32_t smem_u32(const void* p) {
    uint32_t a;
    asm("{ .reg .u64 t; cvta.to.shared.u64 t, %1; cvt.u32.u64 %0, t; }" : "=r"(a) : "l"(p));
    return a;
}
__device__ __forceinline__ void cp16(uint32_t s, const void* g) {
    asm volatile("cp.async.cg.shared.global [%0], [%1], 16;" :: "r"(s), "l"(g));
}
#define CP_COMMIT()  asm volatile("cp.async.commit_group;" ::: "memory")
#define CP_WAIT_0()  asm volatile("cp.async.wait_group 0;" ::: "memory")

__device__ __forceinline__ void ldm_x4(uint32_t* r, uint32_t a) {
    asm volatile("ldmatrix.sync.aligned.m8n8.x4.shared.b16 {%0,%1,%2,%3}, [%4];"
        : "=r"(r[0]), "=r"(r[1]), "=r"(r[2]), "=r"(r[3]) : "r"(a));
}
__device__ __forceinline__ void ldm_x4_t(uint32_t* r, uint32_t a) {
    asm volatile("ldmatrix.sync.aligned.m8n8.x4.trans.shared.b16 {%0,%1,%2,%3}, [%4];"
        : "=r"(r[0]), "=r"(r[1]), "=r"(r[2]), "=r"(r[3]) : "r"(a));
}
__device__ __forceinline__ void mma_bf16(float* d, const uint32_t* a,
                                         uint32_t b0, uint32_t b1) {
    asm volatile(
        "mma.sync.aligned.m16n8k16.row.col.f32.bf16.bf16.f32 "
        "{%0,%1,%2,%3}, {%4,%5,%6,%7}, {%8,%9}, {%0,%1,%2,%3};"
        : "+f"(d[0]), "+f"(d[1]), "+f"(d[2]), "+f"(d[3])
        : "r"(a[0]), "r"(a[1]), "r"(a[2]), "r"(a[3]), "r"(b0), "r"(b1));
}
__device__ __forceinline__ void mma_f16(float* d, const uint32_t* a,
                                        uint32_t b0, uint32_t b1) {
    asm volatile(
        "mma.sync.aligned.m16n8k16.row.col.f32.f16.f16.f32 "
        "{%0,%1,%2,%3}, {%4,%5,%6,%7}, {%8,%9}, {%0,%1,%2,%3};"
        : "+f"(d[0]), "+f"(d[1]), "+f"(d[2]), "+f"(d[3])
        : "r"(a[0]), "r"(a[1]), "r"(a[2]), "r"(a[3]), "r"(b0), "r"(b1));
}
__device__ __forceinline__ void pack_hl_f16(float p0, float p1, uint32_t& h, uint32_t& l) {
    __half h0 = __float2half_rn(p0), h1 = __float2half_rn(p1);
    h = (uint32_t)__half_as_ushort(h0) | ((uint32_t)__half_as_ushort(h1) << 16);
    __half l0 = __float2half_rn(p0 - __half2float(h0));
    __half l1 = __float2half_rn(p1 - __half2float(h1));
    l = (uint32_t)__half_as_ushort(l0) | ((uint32_t)__half_as_ushort(l1) << 16);
}

// ---------------- fused split: x,Wqkv -> bf16 pair; Wout -> fp16 single -----
#define XN4   (Mv * Kv / 4)
#define WQN4  (QKV_N * Kv / 4)
#define WON4  (Dv * Kv / 4)

__global__ __launch_bounds__(256) void split_all_kernel(const float* __restrict__ x,
                                                        const float* __restrict__ wq,
                                                        const float* __restrict__ wo,
                                                        __nv_bfloat16* __restrict__ xh,
                                                        __nv_bfloat16* __restrict__ xl,
                                                        __nv_bfloat16* __restrict__ wqh,
                                                        __nv_bfloat16* __restrict__ wql,
                                                        __half* __restrict__ woh) {
    int i = blockIdx.x * blockDim.x + threadIdx.x;
    if (i >= XN4 + WQN4 + WON4) return;
    if (i >= XN4 + WQN4) {
        i -= XN4 + WQN4;
        float4 v = reinterpret_cast<const float4*>(wo)[i];
        ushort4 h;
        h.x = __half_as_ushort(__float2half_rn(v.x));
        h.y = __half_as_ushort(__float2half_rn(v.y));
        h.z = __half_as_ushort(__float2half_rn(v.z));
        h.w = __half_as_ushort(__float2half_rn(v.w));
        reinterpret_cast<ushort4*>(woh)[i] = h;
        return;
    }
    const float* s; __nv_bfloat16 *hi, *lo;
    if (i < XN4) { s = x; hi = xh; lo = xl; }
    else         { i -= XN4; s = wq; hi = wqh; lo = wql; }
    float4 v = reinterpret_cast<const float4*>(s)[i];
    ushort4 h, l;
    __nv_bfloat16 b;
    b = __float2bfloat16(v.x); h.x = __bfloat16_as_ushort(b);
    l.x = __bfloat16_as_ushort(__float2bfloat16(v.x - __bfloat162float(b)));
    b = __float2bfloat16(v.y); h.y = __bfloat16_as_ushort(b);
    l.y = __bfloat16_as_ushort(__float2bfloat16(v.y - __bfloat162float(b)));
    b = __float2bfloat16(v.z); h.z = __bfloat16_as_ushort(b);
    l.z = __bfloat16_as_ushort(__float2bfloat16(v.z - __bfloat162float(b)));
    b = __float2bfloat16(v.w); h.w = __bfloat16_as_ushort(b);
    l.w = __bfloat16_as_ushort(__float2bfloat16(v.w - __bfloat162float(b)));
    reinterpret_cast<ushort4*>(hi)[i] = h;
    reinterpret_cast<ushort4*>(lo)[i] = l;
}

// ---------------- QKV GEMM: bf16 3-pass, 128x64 tile, 3 CTAs/SM -------------
#define RS      40
#define TILE_A  (128 * RS * 2)
#define TILE_Bt (64  * RS * 2)
#define STG_B   (2 * TILE_A + 2 * TILE_Bt)

#define DO_KSTEP(KO) \
    { \
        uint32_t ah[2][4], bh[2][4]; \
        _Pragma("unroll") \
        for (int i = 0; i < 2; i++) \
            ldm_x4(ah[i], a_base + s + (KO) + (uint32_t)i * (16 * RS * 2)); \
        _Pragma("unroll") \
        for (int j = 0; j < 2; j++) \
            ldm_x4(bh[j], b_base + s + (KO) + (uint32_t)j * (16 * RS * 2)); \
        _Pragma("unroll") \
        for (int i = 0; i < 2; i++) \
            _Pragma("unroll") \
            for (int n = 0; n < 4; n++) \
                mma_bf16(acc[i][n], ah[i], bh[n>>1][n&1], bh[n>>1][2+(n&1)]); \
        uint32_t bl[2][4]; \
        _Pragma("unroll") \
        for (int j = 0; j < 2; j++) \
            ldm_x4(bl[j], b_base + s + (KO) + TILE_Bt + (uint32_t)j * (16 * RS * 2)); \
        _Pragma("unroll") \
        for (int i = 0; i < 2; i++) \
            _Pragma("unroll") \
            for (int n = 0; n < 4; n++) \
                mma_bf16(acc[i][n], ah[i], bl[n>>1][n&1], bl[n>>1][2+(n&1)]); \
        uint32_t al[2][4]; \
        _Pragma("unroll") \
        for (int i = 0; i < 2; i++) \
            ldm_x4(al[i], a_base + s + (KO) + TILE_A + (uint32_t)i * (16 * RS * 2)); \
        _Pragma("unroll") \
        for (int i = 0; i < 2; i++) \
            _Pragma("unroll") \
            for (int n = 0; n < 4; n++) \
                mma_bf16(acc[i][n], al[i], bh[n>>1][n&1], bh[n>>1][2+(n&1)]); \
    }

#define DO_PREFETCH() \
    if (kt + 1 < NCHUNK) { \
        const uint32_t s1 = (uint32_t)((kt + 1) & 1) * STG_B; \
        const int k1 = (kt + 1) * 32; \
        _Pragma("unroll") \
        for (int i = 0; i < 2; i++) { \
            cp16(dsb + s1 + soffA[i],           Ahb + goffA[i] + k1); \
            cp16(dsb + s1 + TILE_A + soffA[i],  Alb + goffA[i] + k1); \
        } \
        cp16(dsb + s1 + 2u*TILE_A + soffB,           Bhb + goffB + k1); \
        cp16(dsb + s1 + 2u*TILE_A + TILE_Bt + soffB, Blb + goffB + k1); \
        CP_COMMIT(); \
    }

__global__ __launch_bounds__(256, 3) void gemm_qkv(const __nv_bfloat16* __restrict__ Ah,
                                                   const __nv_bfloat16* __restrict__ Al,
                                                   const __nv_bfloat16* __restrict__ Bh,
                                                   const __nv_bfloat16* __restrict__ Bl,
                                                   const float* __restrict__ bias) {
    extern __shared__ __align__(1024) char dsm[];
    const uint32_t dsb = smem_u32(dsm);

    const int t    = threadIdx.x;
    const int lane = t & 31;
    const int wid  = t >> 5;
    const int wm   = wid & 3;
    const int wn   = wid >> 2;
    const int m0   = blockIdx.y * 128;
    const int n0   = blockIdx.x * 64;

    int goffA[2]; uint32_t soffA[2];
    #pragma unroll
    for (int i = 0; i < 2; i++) {
        int g   = t + i * 256;
        int row = g >> 2;
        int c8  = (g & 3) * 8;
        goffA[i] = row * Kv + c8;
        soffA[i] = (uint32_t)(row * RS + c8) * 2;
    }
    const int      goffB = (t >> 2) * Kv + (t & 3) * 8;
    const uint32_t soffB = (uint32_t)((t >> 2) * RS + (t & 3) * 8) * 2;

    const __nv_bfloat16* Ahb = Ah + (size_t)m0 * Kv;
    const __nv_bfloat16* Alb = Al + (size_t)m0 * Kv;
    const __nv_bfloat16* Bhb = Bh + (size_t)n0 * Kv;
    const __nv_bfloat16* Blb = Bl + (size_t)n0 * Kv;

    const uint32_t a_base = dsb + (uint32_t)((wm * 32 + (lane & 15)) * RS + (lane >> 4) * 8) * 2;
    const uint32_t b_base = dsb + 2u * TILE_A
                          + (uint32_t)((wn * 32 + (lane & 15)) * RS + (lane >> 4) * 8) * 2;

    float acc[2][4][4];
    #pragma unroll
    for (int i = 0; i < 2; i++)
        #pragma unroll
        for (int n = 0; n < 4; n++)
            #pragma unroll
            for (int r = 0; r < 4; r++) acc[i][n][r] = 0.0f;

    #pragma unroll
    for (int i = 0; i < 2; i++) {
        cp16(dsb + soffA[i],          Ahb + goffA[i]);
        cp16(dsb + TILE_A + soffA[i], Alb + goffA[i]);
    }
    cp16(dsb + 2u*TILE_A + soffB,           Bhb + goffB);
    cp16(dsb + 2u*TILE_A + TILE_Bt + soffB, Blb + goffB);
    CP_COMMIT();

    const int NCHUNK = Kv / 32;
    for (int kt = 0; kt < NCHUNK; kt++) {
        const uint32_t s = (uint32_t)(kt & 1) * STG_B;
        CP_WAIT_0();
        __syncthreads();
        if (wid & 1) {
            DO_KSTEP(32)
            DO_PREFETCH()
            DO_KSTEP(0)
        } else {
            DO_KSTEP(0)
            DO_PREFETCH()
            DO_KSTEP(32)
        }
    }

    // epilogue: Q -> fp16 hi/lo pair; K,V -> fp16 single
    #pragma unroll
    for (int i = 0; i < 2; i++)
        #pragma unroll
        for (int n = 0; n < 4; n++)
            #pragma unroll
            for (int r = 0; r < 4; r++) {
                int row = m0 + wm * 32 + i * 16 + (lane >> 2) + (r >> 1) * 8;
                int col = n0 + wn * 32 + n * 8 + (lane & 3) * 2 + (r & 1);
                float v = acc[i][n][r] + __ldg(bias + col);
                int bb = row >> 11;
                int tt = row & (Tv - 1);
                int h  = col / 192;
                int rr = col - h * 192;
                size_t off = (((size_t)(bb * Hv + h)) * Tv + tt) * HDv + (rr & 63);
                if (rr < 64) {
                    __half hi = __float2half_rn(v);
                    g_Qh[off] = hi;
                    g_Ql[off] = __float2half_rn(v - __half2float(hi));
                } else if (rr < 128) {
                    g_Kh[off] = __float2half_rn(v);
                } else {
                    g_Vh[off] = __float2half_rn(v);
                }
            }
}

// ---------------- out-proj GEMM: fp16 2-pass (A pair x B single) ------------
#define OSTG_B  (2 * TILE_A + TILE_Bt)   // 25600 per stage

#define DO_KSTEP_O(KO) \
    { \
        uint32_t af[2][4], bf_[2][4]; \
        _Pragma("unroll") \
        for (int i = 0; i < 2; i++) \
            ldm_x4(af[i], a_base + s + (KO) + (uint32_t)i * (16 * RS * 2)); \
        _Pragma("unroll") \
        for (int j = 0; j < 2; j++) \
            ldm_x4(bf_[j], b_base + s + (KO) + (uint32_t)j * (16 * RS * 2)); \
        _Pragma("unroll") \
        for (int i = 0; i < 2; i++) \
            _Pragma("unroll") \
            for (int n = 0; n < 4; n++) \
                mma_f16(acc[i][n], af[i], bf_[n>>1][n&1], bf_[n>>1][2+(n&1)]); \
        uint32_t alf[2][4]; \
        _Pragma("unroll") \
        for (int i = 0; i < 2; i++) \
            ldm_x4(alf[i], a_base + s + (KO) + TILE_A + (uint32_t)i * (16 * RS * 2)); \
        _Pragma("unroll") \
        for (int i = 0; i < 2; i++) \
            _Pragma("unroll") \
            for (int n = 0; n < 4; n++) \
                mma_f16(acc[i][n], alf[i], bf_[n>>1][n&1], bf_[n>>1][2+(n&1)]); \
    }

#define DO_PREFETCH_O() \
    if (kt + 1 < NCHUNK) { \
        const uint32_t s1 = (uint32_t)((kt + 1) & 1) * OSTG_B; \
        const int k1 = (kt + 1) * 32; \
        _Pragma("unroll") \
        for (int i = 0; i < 2; i++) { \
            cp16(dsb + s1 + soffA[i],           Ahb + goffA[i] + k1); \
            cp16(dsb + s1 + TILE_A + soffA[i],  Alb + goffA[i] + k1); \
        } \
        cp16(dsb + s1 + 2u*TILE_A + soffB, Bhb + goffB + k1); \
        CP_COMMIT(); \
    }

__global__ __launch_bounds__(256, 3) void gemm_out(const __half* __restrict__ Ah,
                                                   const __half* __restrict__ Al,
                                                   const __half* __restrict__ Bh,
                                                   const float* __restrict__ bias,
                                                   float* __restrict__ C) {
    extern __shared__ __align__(1024) char dsm[];
    const uint32_t dsb = smem_u32(dsm);

    const int t    = threadIdx.x;
    const int lane = t & 31;
    const int wid  = t >> 5;
    const int wm   = wid & 3;
    const int wn   = wid >> 2;
    const int m0   = blockIdx.y * 128;
    const int n0   = blockIdx.x * 64;

    int goffA[2]; uint32_t soffA[2];
    #pragma unroll
    for (int i = 0; i < 2; i++) {
        int g   = t + i * 256;
        int row = g >> 2;
        int c8  = (g & 3) * 8;
        goffA[i] = row * Kv + c8;
        soffA[i] = (uint32_t)(row * RS + c8) * 2;
    }
    const int      goffB = (t >> 2) * Kv + (t & 3) * 8;
    const uint32_t soffB = (uint32_t)((t >> 2) * RS + (t & 3) * 8) * 2;

    const __half* Ahb = Ah + (size_t)m0 * Kv;
    const __half* Alb = Al + (size_t)m0 * Kv;
    const __half* Bhb = Bh + (size_t)n0 * Kv;

    const uint32_t a_base = dsb + (uint32_t)((wm * 32 + (lane & 15)) * RS + (lane >> 4) * 8) * 2;
    const uint32_t b_base = dsb + 2u * TILE_A
                          + (uint32_t)((wn * 32 + (lane & 15)) * RS + (lane >> 4) * 8) * 2;

    float acc[2][4][4];
    #pragma unroll
    for (int i = 0; i < 2; i++)
        #pragma unroll
        for (int n = 0; n < 4; n++)
            #pragma unroll
            for (int r = 0; r < 4; r++) acc[i][n][r] = 0.0f;

    #pragma unroll
    for (int i = 0; i < 2; i++) {
        cp16(dsb + soffA[i],          Ahb + goffA[i]);
        cp16(dsb + TILE_A + soffA[i], Alb + goffA[i]);
    }
    cp16(dsb + 2u*TILE_A + soffB, Bhb + goffB);
    CP_COMMIT();

    const int NCHUNK = Kv / 32;
    for (int kt = 0; kt < NCHUNK; kt++) {
        const uint32_t s = (uint32_t)(kt & 1) * OSTG_B;
        CP_WAIT_0();
        __syncthreads();
        if (wid & 1) {
            DO_KSTEP_O(32)
            DO_PREFETCH_O()
            DO_KSTEP_O(0)
        } else {
            DO_KSTEP_O(0)
            DO_PREFETCH_O()
            DO_KSTEP_O(32)
        }
    }

    #pragma unroll
    for (int i = 0; i < 2; i++)
        #pragma unroll
        for (int n = 0; n < 4; n++) {
            int row = m0 + wm * 32 + i * 16 + (lane >> 2);
            int col = n0 + wn * 32 + n * 8 + (lane & 3) * 2;
            float b0 = __ldg(bias + col), b1 = __ldg(bias + col + 1);
            float2 v0 = make_float2(acc[i][n][0] + b0, acc[i][n][1] + b1);
            float2 v1 = make_float2(acc[i][n][2] + b0, acc[i][n][3] + b1);
            *reinterpret_cast<float2*>(C + (size_t)row * Dv + col)       = v0;
            *reinterpret_cast<float2*>(C + (size_t)(row + 8) * Dv + col) = v1;
        }
}

// ---------------- flash attention: fp16 2-pass, 2 CTAs/SM -------------------
#define FRS        72
#define FQ_TILE_B  (128 * FRS * 2)          // 18432
#define FK_TILE_B  (64 * FRS * 2)           // 9216
#define FST_B      (2 * FK_TILE_B)          // 18432 (Kh, Vh)
#define FLASH_SMEM (2 * FQ_TILE_B + 2 * FST_B)  // 73728

__global__ __launch_bounds__(256, 2) void flash_mma() {
    extern __shared__ __align__(1024) char fsm[];
    const uint32_t base = smem_u32(fsm);

    const int t    = threadIdx.x;
    const int lane = t & 31;
    const int wid  = t >> 5;
    const int bh   = blockIdx.y;
    const int qt   = (Tv / 128 - 1) - blockIdx.x;   // big tiles first
    const int q0   = qt * 128;
    const int NKT  = 2 * qt + 2;

    const __half* Qhg = g_Qh + ((size_t)bh * Tv + q0) * HDv;
    const __half* Qlg = g_Ql + ((size_t)bh * Tv + q0) * HDv;
    const __half* Khg = g_Kh + (size_t)bh * Tv * HDv;
    const __half* Vhg = g_Vh + (size_t)bh * Tv * HDv;

    // Q tile (hi + lo)
    #pragma unroll
    for (int i = 0; i < 4; i++) {
        int g = t + i * 256;
        int r = g >> 3;
        int c8 = (g & 7) * 8;
        uint32_t so = (uint32_t)(r * FRS + c8) * 2;
        cp16(base + so,             Qhg + r * HDv + c8);
        cp16(base + FQ_TILE_B + so, Qlg + r * HDv + c8);
    }
    CP_COMMIT();
    // stage 0 K,V
    #pragma unroll
    for (int i = 0; i < 2; i++) {
        int g = t + i * 256;
        int r = g >> 3, c8 = (g & 7) * 8;
        uint32_t st = base + 2 * FQ_TILE_B;
        uint32_t so = (uint32_t)(r * FRS + c8) * 2;
        int go = r * HDv + c8;
        cp16(st + so,             Khg + go);
        cp16(st + FK_TILE_B + so, Vhg + go);
    }
    CP_COMMIT();

    const int qw0 = q0 + wid * 16;
    float m_[2] = {-INFINITY, -INFINITY};
    float l_[2] = {0.0f, 0.0f};
    float o[8][4];
    #pragma unroll
    for (int n = 0; n < 8; n++)
        #pragma unroll
        for (int e = 0; e < 4; e++) o[n][e] = 0.0f;

    const uint32_t q_lmb  = base + (uint32_t)((wid * 16 + (lane & 15)) * FRS + (lane >> 4) * 8) * 2;
    const uint32_t k_lane = (uint32_t)((lane & 15) * FRS + (lane >> 4) * 8) * 2;
    const uint32_t v_lane = (uint32_t)(((lane & 7) + ((lane >> 4) << 3)) * FRS + ((lane >> 3) & 1) * 8) * 2;

    for (int kt = 0; kt < NKT; kt++) {
        const uint32_t st = base + 2 * FQ_TILE_B + (uint32_t)(kt & 1) * FST_B;
        CP_WAIT_0();
        __syncthreads();
        if (kt + 1 < NKT) {
            const uint32_t st1 = base + 2 * FQ_TILE_B + (uint32_t)((kt + 1) & 1) * FST_B;
            const int kr = (kt + 1) * 64;
            #pragma unroll
            for (int i = 0; i < 2; i++) {
                int g = t + i * 256;
                int r = g >> 3, c8 = (g & 7) * 8;
                uint32_t so = (uint32_t)(r * FRS + c8) * 2;
                int go = (kr + r) * HDv + c8;
                cp16(st1 + so,             Khg + go);
                cp16(st1 + FK_TILE_B + so, Vhg + go);
            }
            CP_COMMIT();
        }

        const int k0 = kt * 64;
        if (k0 <= qw0 + 15) {
            // ---- S = (Qh+Ql) Kh^T : 2 passes ----
            float sa[8][4];
            #pragma unroll
            for (int n = 0; n < 8; n++)
                #pragma unroll
                for (int e = 0; e < 4; e++) sa[n][e] = 0.0f;

            #pragma unroll
            for (int kg = 0; kg < 4; kg++) {
                uint32_t qhf[4], qlf[4];
                ldm_x4(qhf, q_lmb + kg * 32);
                ldm_x4(qlf, q_lmb + FQ_TILE_B + kg * 32);
                uint32_t kb[4][4];
                #pragma unroll
                for (int np = 0; np < 4; np++)
                    ldm_x4(kb[np], st + k_lane + (uint32_t)(np * 16 * FRS * 2) + kg * 32);
                #pragma unroll
                for (int np = 0; np < 4; np++) {
                    mma_f16(sa[2*np],   qhf, kb[np][0], kb[np][2]);
                    mma_f16(sa[2*np+1], qhf, kb[np][1], kb[np][3]);
                }
                #pragma unroll
                for (int np = 0; np < 4; np++) {
                    mma_f16(sa[2*np],   qlf, kb[np][0], kb[np][2]);
                    mma_f16(sa[2*np+1], qlf, kb[np][1], kb[np][3]);
                }
            }

            // ---- scale + causal mask ----
            const int r0 = qw0 + (lane >> 2);
            #pragma unroll
            for (int n = 0; n < 8; n++)
                #pragma unroll
                for (int e = 0; e < 4; e++) {
                    float v = sa[n][e] * 0.125f;
                    int rr = r0 + (e >> 1) * 8;
                    int cc = k0 + n * 8 + (lane & 3) * 2 + (e & 1);
                    sa[n][e] = (cc > rr) ? -INFINITY : v;
                }

            // ---- online softmax ----
            float corr[2];
            #pragma unroll
            for (int rh = 0; rh < 2; rh++) {
                float mx = -INFINITY;
                #pragma unroll
                for (int n = 0; n < 8; n++)
                    mx = fmaxf(mx, fmaxf(sa[n][2*rh], sa[n][2*rh+1]));
                mx = fmaxf(mx, __shfl_xor_sync(0xffffffffu, mx, 1));
                mx = fmaxf(mx, __shfl_xor_sync(0xffffffffu, mx, 2));
                float mnew = fmaxf(m_[rh], mx);
                corr[rh] = __expf(m_[rh] - mnew);
                m_[rh] = mnew;
                float rs = 0.0f;
                #pragma unroll
                for (int n = 0; n < 8; n++) {
                    float p0 = __expf(sa[n][2*rh]   - mnew);
                    float p1 = __expf(sa[n][2*rh+1] - mnew);
                    sa[n][2*rh] = p0; sa[n][2*rh+1] = p1;
                    rs += p0 + p1;
                }
                rs += __shfl_xor_sync(0xffffffffu, rs, 1);
                rs += __shfl_xor_sync(0xffffffffu, rs, 2);
                l_[rh] = l_[rh] * corr[rh] + rs;
            }
            #pragma unroll
            for (int n = 0; n < 8; n++) {
                o[n][0] *= corr[0]; o[n][1] *= corr[0];
                o[n][2] *= corr[1]; o[n][3] *= corr[1];
            }

            // ---- O += (Ph+Pl) Vh : 2 passes ----
            #pragma unroll
            for (int kg = 0; kg < 4; kg++) {
                uint32_t pah[4], pal[4];
                pack_hl_f16(sa[2*kg][0],   sa[2*kg][1],   pah[0], pal[0]);
                pack_hl_f16(sa[2*kg][2],   sa[2*kg][3],   pah[1], pal[1]);
                pack_hl_f16(sa[2*kg+1][0], sa[2*kg+1][1], pah[2], pal[2]);
                pack_hl_f16(sa[2*kg+1][2], sa[2*kg+1][3], pah[3], pal[3]);
                uint32_t vb[4][4];
                #pragma unroll
                for (int ndp = 0; ndp < 4; ndp++)
                    ldm_x4_t(vb[ndp], st + FK_TILE_B + v_lane
                                      + (uint32_t)(kg * 16 * FRS * 2) + ndp * 32);
                #pragma unroll
                for (int ndp = 0; ndp < 4; ndp++) {
                    mma_f16(o[2*ndp],   pah, vb[ndp][0], vb[ndp][2]);
                    mma_f16(o[2*ndp+1], pah, vb[ndp][1], vb[ndp][3]);
                }
                #pragma unroll
                for (int ndp = 0; ndp < 4; ndp++) {
                    mma_f16(o[2*ndp],   pal, vb[ndp][0], vb[ndp][2]);
                    mma_f16(o[2*ndp+1], pal, vb[ndp][1], vb[ndp][3]);
                }
            }
        }
    }

    // ---- finalize: write fp16 hi/lo attention output ----
    const int bb = bh >> 4;
    const int h  = bh & 15;
    const float i0 = 1.0f / l_[0], i1 = 1.0f / l_[1];
    const int row = q0 + wid * 16 + (lane >> 2);
    const size_t base0 = ((size_t)(bb * Tv) + row) * Dv;
    const size_t base1 = base0 + (size_t)8 * Dv;
    #pragma unroll
    for (int nd = 0; nd < 8; nd++) {
        int col = h * 64 + nd * 8 + (lane & 3) * 2;
        uint32_t h0, l0, h1, l1;
        pack_hl_f16(o[nd][0] * i0, o[nd][1] * i0, h0, l0);
        pack_hl_f16(o[nd][2] * i1, o[nd][3] * i1, h1, l1);
        *reinterpret_cast<uint32_t*>(&g_ah[base0 + col]) = h0;
        *reinterpret_cast<uint32_t*>(&g_al[base0 + col]) = l0;
        *reinterpret_cast<uint32_t*>(&g_ah[base1 + col]) = h1;
        *reinterpret_cast<uint32_t*>(&g_al[base1 + col]) = l1;
    }
}

// ---------------------------------------------------------------------------
extern "C" void kernel_launch(void* const* d_in, const int* in_sizes, int n_in,
                              void* d_out, int out_size) {
    const float* x    = (const float*)d_in[0];
    const float* Wqkv = (const float*)d_in[1];
    const float* bqkv = (const float*)d_in[2];
    const float* Wout = (const float*)d_in[3];
    const float* bout = (const float*)d_in[4];
    float* out = (float*)d_out;

    void *xh, *xl, *wqh, *wql, *ah, *al, *woh;
    cudaGetSymbolAddress(&xh,  g_xh);  cudaGetSymbolAddress(&xl,  g_xl);
    cudaGetSymbolAddress(&wqh, g_wqh); cudaGetSymbolAddress(&wql, g_wql);
    cudaGetSymbolAddress(&ah,  g_ah);  cudaGetSymbolAddress(&al,  g_al);
    cudaGetSymbolAddress(&woh, g_woh);

    cudaFuncSetAttribute(gemm_qkv,  cudaFuncAttributeMaxDynamicSharedMemorySize, 2 * STG_B);
    cudaFuncSetAttribute(gemm_out,  cudaFuncAttributeMaxDynamicSharedMemorySize, 2 * OSTG_B);
    cudaFuncSetAttribute(flash_mma, cudaFuncAttributeMaxDynamicSharedMemorySize, FLASH_SMEM);

    // splits: x,Wqkv -> bf16 pair; Wout -> fp16 single
    split_all_kernel<<<(XN4 + WQN4 + WON4 + 255) / 256, 256>>>(
        x, Wqkv, Wout,
        (__nv_bfloat16*)xh,  (__nv_bfloat16*)xl,
        (__nv_bfloat16*)wqh, (__nv_bfloat16*)wql,
        (__half*)woh);

    // 1) QKV projection (bf16 3-pass) -> fp16 Q pair + fp16 K,V singles
    gemm_qkv<<<dim3(QKV_N / 64, Mv / 128), 256, 2 * STG_B>>>(
        (__nv_bfloat16*)xh, (__nv_bfloat16*)xl,
        (__nv_bfloat16*)wqh, (__nv_bfloat16*)wql, bqkv);

    // 2) causal flash attention (fp16 2-pass, 2 CTAs/SM)
    flash_mma<<<dim3(Tv / 128, Bv * Hv), 256, FLASH_SMEM>>>();

    // 3) output projection (fp16 2-pass)
    gemm_out<<<dim3(Dv / 64, Mv / 128), 256, 2 * OSTG_B>>>(
        (const __half*)ah, (const __half*)al, (const __half*)woh, bout, out);
}

// round 14
// speedup vs baseline: 1.3870x; 1.1093x over previous
#include <cuda_runtime.h>
#include <cuda_fp16.h>
#include <math.h>
#include <stdint.h>

#define Bv 2
#define Tv 2048
#define Dv 1024
#define Hv 16
#define HDv 64
#define Mv 4096          // B*T
#define Kv 1024
#define QKV_N 3072

// ---------------- device scratch (no allocations allowed) ------------------
__device__ __align__(16) __half g_Qh[Bv*Hv*Tv*HDv], g_Ql[Bv*Hv*Tv*HDv];  // fp16 pair
__device__ __align__(16) __half g_Kh[Bv*Hv*Tv*HDv];                       // fp16 single
__device__ __align__(16) __half g_Vh[Bv*Hv*Tv*HDv];                       // fp16 single

__device__ __align__(16) __half g_xh[Mv*Kv], g_xl[Mv*Kv];                 // fp16 pair
__device__ __align__(16) __half g_wqh[QKV_N*Kv];                          // fp16 single
__device__ __align__(16) __half g_ah[Mv*Kv], g_al[Mv*Kv];                 // fp16 pair
__device__ __align__(16) __half g_woh[Dv*Kv];                             // fp16 single

// ---------------- PTX helpers ------------------------------------------------
__device__ __forceinline__ uint32_t smem_u32(const void* p) {
    uint32_t a;
    asm("{ .reg .u64 t; cvta.to.shared.u64 t, %1; cvt.u32.u64 %0, t; }" : "=r"(a) : "l"(p));
    return a;
}
__device__ __forceinline__ void cp16(uint32_t s, const void* g) {
    asm volatile("cp.async.cg.shared.global [%0], [%1], 16;" :: "r"(s), "l"(g));
}
#define CP_COMMIT()  asm volatile("cp.async.commit_group;" ::: "memory")
#define CP_WAIT_0()  asm volatile("cp.async.wait_group 0;" ::: "memory")

__device__ __forceinline__ void ldm_x4(uint32_t* r, uint32_t a) {
    asm volatile("ldmatrix.sync.aligned.m8n8.x4.shared.b16 {%0,%1,%2,%3}, [%4];"
        : "=r"(r[0]), "=r"(r[1]), "=r"(r[2]), "=r"(r[3]) : "r"(a));
}
__device__ __forceinline__ void ldm_x4_t(uint32_t* r, uint32_t a) {
    asm volatile("ldmatrix.sync.aligned.m8n8.x4.trans.shared.b16 {%0,%1,%2,%3}, [%4];"
        : "=r"(r[0]), "=r"(r[1]), "=r"(r[2]), "=r"(r[3]) : "r"(a));
}
__device__ __forceinline__ void mma_f16(float* d, const uint32_t* a,
                                        uint32_t b0, uint32_t b1) {
    asm volatile(
        "mma.sync.aligned.m16n8k16.row.col.f32.f16.f16.f32 "
        "{%0,%1,%2,%3}, {%4,%5,%6,%7}, {%8,%9}, {%0,%1,%2,%3};"
        : "+f"(d[0]), "+f"(d[1]), "+f"(d[2]), "+f"(d[3])
        : "r"(a[0]), "r"(a[1]), "r"(a[2]), "r"(a[3]), "r"(b0), "r"(b1));
}
__device__ __forceinline__ void pack_hl_f16(float p0, float p1, uint32_t& h, uint32_t& l) {
    __half h0 = __float2half_rn(p0), h1 = __float2half_rn(p1);
    h = (uint32_t)__half_as_ushort(h0) | ((uint32_t)__half_as_ushort(h1) << 16);
    __half l0 = __float2half_rn(p0 - __half2float(h0));
    __half l1 = __float2half_rn(p1 - __half2float(h1));
    l = (uint32_t)__half_as_ushort(l0) | ((uint32_t)__half_as_ushort(l1) << 16);
}

// ---------------- fused split: x -> fp16 pair; Wqkv,Wout -> fp16 single -----
#define XN4   (Mv * Kv / 4)
#define WQN4  (QKV_N * Kv / 4)
#define WON4  (Dv * Kv / 4)

__global__ __launch_bounds__(256) void split_all_kernel(const float* __restrict__ x,
                                                        const float* __restrict__ wq,
                                                        const float* __restrict__ wo,
                                                        __half* __restrict__ xh,
                                                        __half* __restrict__ xl,
                                                        __half* __restrict__ wqh,
                                                        __half* __restrict__ woh) {
    int i = blockIdx.x * blockDim.x + threadIdx.x;
    if (i >= XN4 + WQN4 + WON4) return;
    if (i < XN4) {
        float4 v = reinterpret_cast<const float4*>(x)[i];
        ushort4 h, l;
        __half b;
        b = __float2half_rn(v.x); h.x = __half_as_ushort(b);
        l.x = __half_as_ushort(__float2half_rn(v.x - __half2float(b)));
        b = __float2half_rn(v.y); h.y = __half_as_ushort(b);
        l.y = __half_as_ushort(__float2half_rn(v.y - __half2float(b)));
        b = __float2half_rn(v.z); h.z = __half_as_ushort(b);
        l.z = __half_as_ushort(__float2half_rn(v.z - __half2float(b)));
        b = __float2half_rn(v.w); h.w = __half_as_ushort(b);
        l.w = __half_as_ushort(__float2half_rn(v.w - __half2float(b)));
        reinterpret_cast<ushort4*>(xh)[i] = h;
        reinterpret_cast<ushort4*>(xl)[i] = l;
        return;
    }
    const float* s; __half* dst;
    if (i < XN4 + WQN4) { i -= XN4;        s = wq; dst = wqh; }
    else                { i -= XN4 + WQN4; s = wo; dst = woh; }
    float4 v = reinterpret_cast<const float4*>(s)[i];
    ushort4 h;
    h.x = __half_as_ushort(__float2half_rn(v.x));
    h.y = __half_as_ushort(__float2half_rn(v.y));
    h.z = __half_as_ushort(__float2half_rn(v.z));
    h.w = __half_as_ushort(__float2half_rn(v.w));
    reinterpret_cast<ushort4*>(dst)[i] = h;
}

// ---------------- unified fp16 2-pass GEMM: C = (Ah+Al) @ Bh^T + bias -------
// 128x64 CTA tile, 8 warps (warp 32x32), BK=32, 3 CTAs/SM.
// MODE 0: scatter Q (fp16 pair) / K,V (fp16 single); MODE 1: fp32 C + bias.
#define RS      40
#define TILE_A  (128 * RS * 2)          // 10240
#define TILE_Bt (64  * RS * 2)          // 5120
#define STG_B   (2 * TILE_A + TILE_Bt)  // 25600 per stage

#define DO_KSTEP(KO) \
    { \
        uint32_t af[2][4], bf_[2][4]; \
        _Pragma("unroll") \
        for (int i = 0; i < 2; i++) \
            ldm_x4(af[i], a_base + s + (KO) + (uint32_t)i * (16 * RS * 2)); \
        _Pragma("unroll") \
        for (int j = 0; j < 2; j++) \
            ldm_x4(bf_[j], b_base + s + (KO) + (uint32_t)j * (16 * RS * 2)); \
        _Pragma("unroll") \
        for (int i = 0; i < 2; i++) \
            _Pragma("unroll") \
            for (int n = 0; n < 4; n++) \
                mma_f16(acc[i][n], af[i], bf_[n>>1][n&1], bf_[n>>1][2+(n&1)]); \
        uint32_t alf[2][4]; \
        _Pragma("unroll") \
        for (int i = 0; i < 2; i++) \
            ldm_x4(alf[i], a_base + s + (KO) + TILE_A + (uint32_t)i * (16 * RS * 2)); \
        _Pragma("unroll") \
        for (int i = 0; i < 2; i++) \
            _Pragma("unroll") \
            for (int n = 0; n < 4; n++) \
                mma_f16(acc[i][n], alf[i], bf_[n>>1][n&1], bf_[n>>1][2+(n&1)]); \
    }

#define DO_PREFETCH() \
    if (kt + 1 < NCHUNK) { \
        const uint32_t s1 = (uint32_t)((kt + 1) & 1) * STG_B; \
        const int k1 = (kt + 1) * 32; \
        _Pragma("unroll") \
        for (int i = 0; i < 2; i++) { \
            cp16(dsb + s1 + soffA[i],           Ahb + goffA[i] + k1); \
            cp16(dsb + s1 + TILE_A + soffA[i],  Alb + goffA[i] + k1); \
        } \
        cp16(dsb + s1 + 2u*TILE_A + soffB, Bhb + goffB + k1); \
        CP_COMMIT(); \
    }

__global__ __launch_bounds__(256, 3) void gemm_f16(const __half* __restrict__ Ah,
                                                   const __half* __restrict__ Al,
                                                   const __half* __restrict__ Bh,
                                                   const float* __restrict__ bias,
                                                   float* __restrict__ C, int MODE) {
    extern __shared__ __align__(1024) char dsm[];
    const uint32_t dsb = smem_u32(dsm);

    const int t    = threadIdx.x;
    const int lane = t & 31;
    const int wid  = t >> 5;
    const int wm   = wid & 3;
    const int wn   = wid >> 2;
    const int m0   = blockIdx.y * 128;
    const int n0   = blockIdx.x * 64;

    int goffA[2]; uint32_t soffA[2];
    #pragma unroll
    for (int i = 0; i < 2; i++) {
        int g   = t + i * 256;
        int row = g >> 2;
        int c8  = (g & 3) * 8;
        goffA[i] = row * Kv + c8;
        soffA[i] = (uint32_t)(row * RS + c8) * 2;
    }
    const int      goffB = (t >> 2) * Kv + (t & 3) * 8;
    const uint32_t soffB = (uint32_t)((t >> 2) * RS + (t & 3) * 8) * 2;

    const __half* Ahb = Ah + (size_t)m0 * Kv;
    const __half* Alb = Al + (size_t)m0 * Kv;
    const __half* Bhb = Bh + (size_t)n0 * Kv;

    const uint32_t a_base = dsb + (uint32_t)((wm * 32 + (lane & 15)) * RS + (lane >> 4) * 8) * 2;
    const uint32_t b_base = dsb + 2u * TILE_A
                          + (uint32_t)((wn * 32 + (lane & 15)) * RS + (lane >> 4) * 8) * 2;

    float acc[2][4][4];
    #pragma unroll
    for (int i = 0; i < 2; i++)
        #pragma unroll
        for (int n = 0; n < 4; n++)
            #pragma unroll
            for (int r = 0; r < 4; r++) acc[i][n][r] = 0.0f;

    #pragma unroll
    for (int i = 0; i < 2; i++) {
        cp16(dsb + soffA[i],          Ahb + goffA[i]);
        cp16(dsb + TILE_A + soffA[i], Alb + goffA[i]);
    }
    cp16(dsb + 2u*TILE_A + soffB, Bhb + goffB);
    CP_COMMIT();

    const int NCHUNK = Kv / 32;
    for (int kt = 0; kt < NCHUNK; kt++) {
        const uint32_t s = (uint32_t)(kt & 1) * STG_B;
        CP_WAIT_0();
        __syncthreads();
        if (wid & 1) {
            DO_KSTEP(32)
            DO_PREFETCH()
            DO_KSTEP(0)
        } else {
            DO_KSTEP(0)
            DO_PREFETCH()
            DO_KSTEP(32)
        }
    }

    if (MODE == 0) {
        // scatter: Q -> fp16 pair; K,V -> fp16 single
        #pragma unroll
        for (int i = 0; i < 2; i++)
            #pragma unroll
            for (int n = 0; n < 4; n++)
                #pragma unroll
                for (int r = 0; r < 4; r++) {
                    int row = m0 + wm * 32 + i * 16 + (lane >> 2) + (r >> 1) * 8;
                    int col = n0 + wn * 32 + n * 8 + (lane & 3) * 2 + (r & 1);
                    float v = acc[i][n][r] + __ldg(bias + col);
                    int bb = row >> 11;
                    int tt = row & (Tv - 1);
                    int h  = col / 192;
                    int rr = col - h * 192;
                    size_t off = (((size_t)(bb * Hv + h)) * Tv + tt) * HDv + (rr & 63);
                    if (rr < 64) {
                        __half hi = __float2half_rn(v);
                        g_Qh[off] = hi;
                        g_Ql[off] = __float2half_rn(v - __half2float(hi));
                    } else if (rr < 128) {
                        g_Kh[off] = __float2half_rn(v);
                    } else {
                        g_Vh[off] = __float2half_rn(v);
                    }
                }
    } else {
        #pragma unroll
        for (int i = 0; i < 2; i++)
            #pragma unroll
            for (int n = 0; n < 4; n++) {
                int row = m0 + wm * 32 + i * 16 + (lane >> 2);
                int col = n0 + wn * 32 + n * 8 + (lane & 3) * 2;
                float b0 = __ldg(bias + col), b1 = __ldg(bias + col + 1);
                float2 v0 = make_float2(acc[i][n][0] + b0, acc[i][n][1] + b1);
                float2 v1 = make_float2(acc[i][n][2] + b0, acc[i][n][3] + b1);
                *reinterpret_cast<float2*>(C + (size_t)row * Dv + col)       = v0;
                *reinterpret_cast<float2*>(C + (size_t)(row + 8) * Dv + col) = v1;
            }
    }
}

// ---------------- flash attention: fp16 2-pass, 2 CTAs/SM (R13) -------------
#define FRS        72
#define FQ_TILE_B  (128 * FRS * 2)
#define FK_TILE_B  (64 * FRS * 2)
#define FST_B      (2 * FK_TILE_B)
#define FLASH_SMEM (2 * FQ_TILE_B + 2 * FST_B)

__global__ __launch_bounds__(256, 2) void flash_mma() {
    extern __shared__ __align__(1024) char fsm[];
    const uint32_t base = smem_u32(fsm);

    const int t    = threadIdx.x;
    const int lane = t & 31;
    const int wid  = t >> 5;
    const int bh   = blockIdx.y;
    const int qt   = (Tv / 128 - 1) - blockIdx.x;   // big tiles first
    const int q0   = qt * 128;
    const int NKT  = 2 * qt + 2;

    const __half* Qhg = g_Qh + ((size_t)bh * Tv + q0) * HDv;
    const __half* Qlg = g_Ql + ((size_t)bh * Tv + q0) * HDv;
    const __half* Khg = g_Kh + (size_t)bh * Tv * HDv;
    const __half* Vhg = g_Vh + (size_t)bh * Tv * HDv;

    #pragma unroll
    for (int i = 0; i < 4; i++) {
        int g = t + i * 256;
        int r = g >> 3;
        int c8 = (g & 7) * 8;
        uint32_t so = (uint32_t)(r * FRS + c8) * 2;
        cp16(base + so,             Qhg + r * HDv + c8);
        cp16(base + FQ_TILE_B + so, Qlg + r * HDv + c8);
    }
    CP_COMMIT();
    #pragma unroll
    for (int i = 0; i < 2; i++) {
        int g = t + i * 256;
        int r = g >> 3, c8 = (g & 7) * 8;
        uint32_t st = base + 2 * FQ_TILE_B;
        uint32_t so = (uint32_t)(r * FRS + c8) * 2;
        int go = r * HDv + c8;
        cp16(st + so,             Khg + go);
        cp16(st + FK_TILE_B + so, Vhg + go);
    }
    CP_COMMIT();

    const int qw0 = q0 + wid * 16;
    float m_[2] = {-INFINITY, -INFINITY};
    float l_[2] = {0.0f, 0.0f};
    float o[8][4];
    #pragma unroll
    for (int n = 0; n < 8; n++)
        #pragma unroll
        for (int e = 0; e < 4; e++) o[n][e] = 0.0f;

    const uint32_t q_lmb  = base + (uint32_t)((wid * 16 + (lane & 15)) * FRS + (lane >> 4) * 8) * 2;
    const uint32_t k_lane = (uint32_t)((lane & 15) * FRS + (lane >> 4) * 8) * 2;
    const uint32_t v_lane = (uint32_t)(((lane & 7) + ((lane >> 4) << 3)) * FRS + ((lane >> 3) & 1) * 8) * 2;

    for (int kt = 0; kt < NKT; kt++) {
        const uint32_t st = base + 2 * FQ_TILE_B + (uint32_t)(kt & 1) * FST_B;
        CP_WAIT_0();
        __syncthreads();
        if (kt + 1 < NKT) {
            const uint32_t st1 = base + 2 * FQ_TILE_B + (uint32_t)((kt + 1) & 1) * FST_B;
            const int kr = (kt + 1) * 64;
            #pragma unroll
            for (int i = 0; i < 2; i++) {
                int g = t + i * 256;
                int r = g >> 3, c8 = (g & 7) * 8;
                uint32_t so = (uint32_t)(r * FRS + c8) * 2;
                int go = (kr + r) * HDv + c8;
                cp16(st1 + so,             Khg + go);
                cp16(st1 + FK_TILE_B + so, Vhg + go);
            }
            CP_COMMIT();
        }

        const int k0 = kt * 64;
        if (k0 <= qw0 + 15) {
            float sa[8][4];
            #pragma unroll
            for (int n = 0; n < 8; n++)
                #pragma unroll
                for (int e = 0; e < 4; e++) sa[n][e] = 0.0f;

            #pragma unroll
            for (int kg = 0; kg < 4; kg++) {
                uint32_t qhf[4], qlf[4];
                ldm_x4(qhf, q_lmb + kg * 32);
                ldm_x4(qlf, q_lmb + FQ_TILE_B + kg * 32);
                uint32_t kb[4][4];
                #pragma unroll
                for (int np = 0; np < 4; np++)
                    ldm_x4(kb[np], st + k_lane + (uint32_t)(np * 16 * FRS * 2) + kg * 32);
                #pragma unroll
                for (int np = 0; np < 4; np++) {
                    mma_f16(sa[2*np],   qhf, kb[np][0], kb[np][2]);
                    mma_f16(sa[2*np+1], qhf, kb[np][1], kb[np][3]);
                }
                #pragma unroll
                for (int np = 0; np < 4; np++) {
                    mma_f16(sa[2*np],   qlf, kb[np][0], kb[np][2]);
                    mma_f16(sa[2*np+1], qlf, kb[np][1], kb[np][3]);
                }
            }

            const int r0 = qw0 + (lane >> 2);
            #pragma unroll
            for (int n = 0; n < 8; n++)
                #pragma unroll
                for (int e = 0; e < 4; e++) {
                    float v = sa[n][e] * 0.125f;
                    int rr = r0 + (e >> 1) * 8;
                    int cc = k0 + n * 8 + (lane & 3) * 2 + (e & 1);
                    sa[n][e] = (cc > rr) ? -INFINITY : v;
                }

            float corr[2];
            #pragma unroll
            for (int rh = 0; rh < 2; rh++) {
                float mx = -INFINITY;
                #pragma unroll
                for (int n = 0; n < 8; n++)
                    mx = fmaxf(mx, fmaxf(sa[n][2*rh], sa[n][2*rh+1]));
                mx = fmaxf(mx, __shfl_xor_sync(0xffffffffu, mx, 1));
                mx = fmaxf(mx, __shfl_xor_sync(0xffffffffu, mx, 2));
                float mnew = fmaxf(m_[rh], mx);
                corr[rh] = __expf(m_[rh] - mnew);
                m_[rh] = mnew;
                float rs = 0.0f;
                #pragma unroll
                for (int n = 0; n < 8; n++) {
                    float p0 = __expf(sa[n][2*rh]   - mnew);
                    float p1 = __expf(sa[n][2*rh+1] - mnew);
                    sa[n][2*rh] = p0; sa[n][2*rh+1] = p1;
                    rs += p0 + p1;
                }
                rs += __shfl_xor_sync(0xffffffffu, rs, 1);
                rs += __shfl_xor_sync(0xffffffffu, rs, 2);
                l_[rh] = l_[rh] * corr[rh] + rs;
            }
            #pragma unroll
            for (int n = 0; n < 8; n++) {
                o[n][0] *= corr[0]; o[n][1] *= corr[0];
                o[n][2] *= corr[1]; o[n][3] *= corr[1];
            }

            #pragma unroll
            for (int kg = 0; kg < 4; kg++) {
                uint32_t pah[4], pal[4];
                pack_hl_f16(sa[2*kg][0],   sa[2*kg][1],   pah[0], pal[0]);
                pack_hl_f16(sa[2*kg][2],   sa[2*kg][3],   pah[1], pal[1]);
                pack_hl_f16(sa[2*kg+1][0], sa[2*kg+1][1], pah[2], pal[2]);
                pack_hl_f16(sa[2*kg+1][2], sa[2*kg+1][3], pah[3], pal[3]);
                uint32_t vb[4][4];
                #pragma unroll
                for (int ndp = 0; ndp < 4; ndp++)
                    ldm_x4_t(vb[ndp], st + FK_TILE_B + v_lane
                                      + (uint32_t)(kg * 16 * FRS * 2) + ndp * 32);
                #pragma unroll
                for (int ndp = 0; ndp < 4; ndp++) {
                    mma_f16(o[2*ndp],   pah, vb[ndp][0], vb[ndp][2]);
                    mma_f16(o[2*ndp+1], pah, vb[ndp][1], vb[ndp][3]);
                }
                #pragma unroll
                for (int ndp = 0; ndp < 4; ndp++) {
                    mma_f16(o[2*ndp],   pal, vb[ndp][0], vb[ndp][2]);
                    mma_f16(o[2*ndp+1], pal, vb[ndp][1], vb[ndp][3]);
                }
            }
        }
    }

    const int bb = bh >> 4;
    const int h  = bh & 15;
    const float i0 = 1.0f / l_[0], i1 = 1.0f / l_[1];
    const int row = q0 + wid * 16 + (lane >> 2);
    const size_t base0 = ((size_t)(bb * Tv) + row) * Dv;
    const size_t base1 = base0 + (size_t)8 * Dv;
    #pragma unroll
    for (int nd = 0; nd < 8; nd++) {
        int col = h * 64 + nd * 8 + (lane & 3) * 2;
        uint32_t h0, l0, h1, l1;
        pack_hl_f16(o[nd][0] * i0, o[nd][1] * i0, h0, l0);
        pack_hl_f16(o[nd][2] * i1, o[nd][3] * i1, h1, l1);
        *reinterpret_cast<uint32_t*>(&g_ah[base0 + col]) = h0;
        *reinterpret_cast<uint32_t*>(&g_al[base0 + col]) = l0;
        *reinterpret_cast<uint32_t*>(&g_ah[base1 + col]) = h1;
        *reinterpret_cast<uint32_t*>(&g_al[base1 + col]) = l1;
    }
}

// ---------------------------------------------------------------------------
extern "C" void kernel_launch(void* const* d_in, const int* in_sizes, int n_in,
                              void* d_out, int out_size) {
    const float* x    = (const float*)d_in[0];
    const float* Wqkv = (const float*)d_in[1];
    const float* bqkv = (const float*)d_in[2];
    const float* Wout = (const float*)d_in[3];
    const float* bout = (const float*)d_in[4];
    float* out = (float*)d_out;

    void *xh, *xl, *wqh, *ah, *al, *woh;
    cudaGetSymbolAddress(&xh,  g_xh);  cudaGetSymbolAddress(&xl,  g_xl);
    cudaGetSymbolAddress(&wqh, g_wqh);
    cudaGetSymbolAddress(&ah,  g_ah);  cudaGetSymbolAddress(&al,  g_al);
    cudaGetSymbolAddress(&woh, g_woh);

    cudaFuncSetAttribute(gemm_f16,  cudaFuncAttributeMaxDynamicSharedMemorySize, 2 * STG_B);
    cudaFuncSetAttribute(flash_mma, cudaFuncAttributeMaxDynamicSharedMemorySize, FLASH_SMEM);

    // splits: x -> fp16 pair; Wqkv, Wout -> fp16 single
    split_all_kernel<<<(XN4 + WQN4 + WON4 + 255) / 256, 256>>>(
        x, Wqkv, Wout,
        (__half*)xh, (__half*)xl, (__half*)wqh, (__half*)woh);

    // 1) QKV projection (fp16 2-pass) -> fp16 Q pair + fp16 K,V singles
    gemm_f16<<<dim3(QKV_N / 64, Mv / 128), 256, 2 * STG_B>>>(
        (const __half*)xh, (const __half*)xl, (const __half*)wqh, bqkv, nullptr, 0);

    // 2) causal flash attention (fp16 2-pass, 2 CTAs/SM)
    flash_mma<<<dim3(Tv / 128, Bv * Hv), 256, FLASH_SMEM>>>();

    // 3) output projection (fp16 2-pass)
    gemm_f16<<<dim3(Dv / 64, Mv / 128), 256, 2 * STG_B>>>(
        (const __half*)ah, (const __half*)al, (const __half*)woh, bout, out, 1);
}

// round 15
// speedup vs baseline: 1.4392x; 1.0376x over previous
#include <cuda_runtime.h>
#include <cuda_fp16.h>
#include <math.h>
#include <stdint.h>

#define Bv 2
#define Tv 2048
#define Dv 1024
#define Hv 16
#define HDv 64
#define Mv 4096          // B*T
#define Kv 1024
#define QKV_N 3072

// ---------------- device scratch (no allocations allowed) ------------------
__device__ __align__(16) __half g_Qh[Bv*Hv*Tv*HDv], g_Ql[Bv*Hv*Tv*HDv];  // fp16 pair
__device__ __align__(16) __half g_Kh[Bv*Hv*Tv*HDv];                       // fp16 single
__device__ __align__(16) __half g_Vh[Bv*Hv*Tv*HDv];                       // fp16 single

__device__ __align__(16) __half g_xh[Mv*Kv], g_xl[Mv*Kv];                 // fp16 pair
__device__ __align__(16) __half g_wqh[QKV_N*Kv];                          // fp16 single
__device__ __align__(16) __half g_ah[Mv*Kv], g_al[Mv*Kv];                 // fp16 pair
__device__ __align__(16) __half g_woh[Dv*Kv];                             // fp16 single

// ---------------- PTX helpers ------------------------------------------------
__device__ __forceinline__ uint32_t smem_u32(const void* p) {
    uint32_t a;
    asm("{ .reg .u64 t; cvta.to.shared.u64 t, %1; cvt.u32.u64 %0, t; }" : "=r"(a) : "l"(p));
    return a;
}
__device__ __forceinline__ void cp16(uint32_t s, const void* g) {
    asm volatile("cp.async.cg.shared.global [%0], [%1], 16;" :: "r"(s), "l"(g));
}
#define CP_COMMIT()  asm volatile("cp.async.commit_group;" ::: "memory")
#define CP_WAIT_0()  asm volatile("cp.async.wait_group 0;" ::: "memory")

__device__ __forceinline__ void ldm_x4(uint32_t* r, uint32_t a) {
    asm volatile("ldmatrix.sync.aligned.m8n8.x4.shared.b16 {%0,%1,%2,%3}, [%4];"
        : "=r"(r[0]), "=r"(r[1]), "=r"(r[2]), "=r"(r[3]) : "r"(a));
}
__device__ __forceinline__ void ldm_x4_t(uint32_t* r, uint32_t a) {
    asm volatile("ldmatrix.sync.aligned.m8n8.x4.trans.shared.b16 {%0,%1,%2,%3}, [%4];"
        : "=r"(r[0]), "=r"(r[1]), "=r"(r[2]), "=r"(r[3]) : "r"(a));
}
__device__ __forceinline__ void mma_f16(float* d, const uint32_t* a,
                                        uint32_t b0, uint32_t b1) {
    asm volatile(
        "mma.sync.aligned.m16n8k16.row.col.f32.f16.f16.f32 "
        "{%0,%1,%2,%3}, {%4,%5,%6,%7}, {%8,%9}, {%0,%1,%2,%3};"
        : "+f"(d[0]), "+f"(d[1]), "+f"(d[2]), "+f"(d[3])
        : "r"(a[0]), "r"(a[1]), "r"(a[2]), "r"(a[3]), "r"(b0), "r"(b1));
}
__device__ __forceinline__ void pack_hl_f16(float p0, float p1, uint32_t& h, uint32_t& l) {
    __half h0 = __float2half_rn(p0), h1 = __float2half_rn(p1);
    h = (uint32_t)__half_as_ushort(h0) | ((uint32_t)__half_as_ushort(h1) << 16);
    __half l0 = __float2half_rn(p0 - __half2float(h0));
    __half l1 = __float2half_rn(p1 - __half2float(h1));
    l = (uint32_t)__half_as_ushort(l0) | ((uint32_t)__half_as_ushort(l1) << 16);
}

// ---------------- fused split: x -> fp16 pair; Wqkv,Wout -> fp16 single -----
#define XN4   (Mv * Kv / 4)
#define WQN4  (QKV_N * Kv / 4)
#define WON4  (Dv * Kv / 4)

__global__ __launch_bounds__(256) void split_all_kernel(const float* __restrict__ x,
                                                        const float* __restrict__ wq,
                                                        const float* __restrict__ wo,
                                                        __half* __restrict__ xh,
                                                        __half* __restrict__ xl,
                                                        __half* __restrict__ wqh,
                                                        __half* __restrict__ woh) {
    int i = blockIdx.x * blockDim.x + threadIdx.x;
    if (i >= XN4 + WQN4 + WON4) return;
    if (i < XN4) {
        float4 v = reinterpret_cast<const float4*>(x)[i];
        ushort4 h, l;
        __half b;
        b = __float2half_rn(v.x); h.x = __half_as_ushort(b);
        l.x = __half_as_ushort(__float2half_rn(v.x - __half2float(b)));
        b = __float2half_rn(v.y); h.y = __half_as_ushort(b);
        l.y = __half_as_ushort(__float2half_rn(v.y - __half2float(b)));
        b = __float2half_rn(v.z); h.z = __half_as_ushort(b);
        l.z = __half_as_ushort(__float2half_rn(v.z - __half2float(b)));
        b = __float2half_rn(v.w); h.w = __half_as_ushort(b);
        l.w = __half_as_ushort(__float2half_rn(v.w - __half2float(b)));
        reinterpret_cast<ushort4*>(xh)[i] = h;
        reinterpret_cast<ushort4*>(xl)[i] = l;
        return;
    }
    const float* s; __half* dst;
    if (i < XN4 + WQN4) { i -= XN4;        s = wq; dst = wqh; }
    else                { i -= XN4 + WQN4; s = wo; dst = woh; }
    float4 v = reinterpret_cast<const float4*>(s)[i];
    ushort4 h;
    h.x = __half_as_ushort(__float2half_rn(v.x));
    h.y = __half_as_ushort(__float2half_rn(v.y));
    h.z = __half_as_ushort(__float2half_rn(v.z));
    h.w = __half_as_ushort(__float2half_rn(v.w));
    reinterpret_cast<ushort4*>(dst)[i] = h;
}

// ---------------- unified fp16 2-pass GEMM: 128x128 tile, 2 CTAs/SM ---------
// 8 warps, warp tile 32x64 (wm=wid&3, wn=wid>>2). BK=32.
// Per k16 step: 8 LDSM : 32 MMA (4:1 ratio).
// MODE 0: scatter Q (fp16 pair) / K,V (fp16 single); MODE 1: fp32 C + bias.
#define RS      40
#define TILE_A  (128 * RS * 2)          // 10240 (also B tile size: 128 rows)
#define STG_B   (3 * TILE_A)            // Ah + Al + Bh = 30720 per stage

#define DO_KSTEP(KO) \
    { \
        uint32_t af[2][4], bf_[4][4]; \
        _Pragma("unroll") \
        for (int i = 0; i < 2; i++) \
            ldm_x4(af[i], a_base + s + (KO) + (uint32_t)i * (16 * RS * 2)); \
        _Pragma("unroll") \
        for (int j = 0; j < 4; j++) \
            ldm_x4(bf_[j], b_base + s + (KO) + (uint32_t)j * (16 * RS * 2)); \
        _Pragma("unroll") \
        for (int i = 0; i < 2; i++) \
            _Pragma("unroll") \
            for (int n = 0; n < 8; n++) \
                mma_f16(acc[i][n], af[i], bf_[n>>1][n&1], bf_[n>>1][2+(n&1)]); \
        uint32_t alf[2][4]; \
        _Pragma("unroll") \
        for (int i = 0; i < 2; i++) \
            ldm_x4(alf[i], a_base + s + (KO) + TILE_A + (uint32_t)i * (16 * RS * 2)); \
        _Pragma("unroll") \
        for (int i = 0; i < 2; i++) \
            _Pragma("unroll") \
            for (int n = 0; n < 8; n++) \
                mma_f16(acc[i][n], alf[i], bf_[n>>1][n&1], bf_[n>>1][2+(n&1)]); \
    }

#define DO_PREFETCH() \
    if (kt + 1 < NCHUNK) { \
        const uint32_t s1 = (uint32_t)((kt + 1) & 1) * STG_B; \
        const int k1 = (kt + 1) * 32; \
        _Pragma("unroll") \
        for (int i = 0; i < 2; i++) { \
            cp16(dsb + s1 + soffA[i],              Ahb + goffA[i] + k1); \
            cp16(dsb + s1 + TILE_A + soffA[i],     Alb + goffA[i] + k1); \
            cp16(dsb + s1 + 2u*TILE_A + soffA[i],  Bhb + goffA[i] + k1); \
        } \
        CP_COMMIT(); \
    }

__global__ __launch_bounds__(256, 2) void gemm_f16(const __half* __restrict__ Ah,
                                                   const __half* __restrict__ Al,
                                                   const __half* __restrict__ Bh,
                                                   const float* __restrict__ bias,
                                                   float* __restrict__ C, int MODE) {
    extern __shared__ __align__(1024) char dsm[];
    const uint32_t dsb = smem_u32(dsm);

    const int t    = threadIdx.x;
    const int lane = t & 31;
    const int wid  = t >> 5;
    const int wm   = wid & 3;        // 0..3 -> 32-row slices
    const int wn   = wid >> 2;       // 0..1 -> 64-col slices
    const int m0   = blockIdx.y * 128;
    const int n0   = blockIdx.x * 128;

    // cp.async geometry: identical for A and B (128 rows x 32 cols, 2 granules/thread)
    int goffA[2]; uint32_t soffA[2];
    #pragma unroll
    for (int i = 0; i < 2; i++) {
        int g   = t + i * 256;
        int row = g >> 2;
        int c8  = (g & 3) * 8;
        goffA[i] = row * Kv + c8;
        soffA[i] = (uint32_t)(row * RS + c8) * 2;
    }

    const __half* Ahb = Ah + (size_t)m0 * Kv;
    const __half* Alb = Al + (size_t)m0 * Kv;
    const __half* Bhb = Bh + (size_t)n0 * Kv;

    const uint32_t a_base = dsb + (uint32_t)((wm * 32 + (lane & 15)) * RS + (lane >> 4) * 8) * 2;
    const uint32_t b_base = dsb + 2u * TILE_A
                          + (uint32_t)((wn * 64 + (lane & 15)) * RS + (lane >> 4) * 8) * 2;

    float acc[2][8][4];
    #pragma unroll
    for (int i = 0; i < 2; i++)
        #pragma unroll
        for (int n = 0; n < 8; n++)
            #pragma unroll
            for (int r = 0; r < 4; r++) acc[i][n][r] = 0.0f;

    // prologue: chunk 0
    #pragma unroll
    for (int i = 0; i < 2; i++) {
        cp16(dsb + soffA[i],              Ahb + goffA[i]);
        cp16(dsb + TILE_A + soffA[i],     Alb + goffA[i]);
        cp16(dsb + 2u*TILE_A + soffA[i],  Bhb + goffA[i]);
    }
    CP_COMMIT();

    const int NCHUNK = Kv / 32;
    for (int kt = 0; kt < NCHUNK; kt++) {
        const uint32_t s = (uint32_t)(kt & 1) * STG_B;
        CP_WAIT_0();
        __syncthreads();   // single barrier per chunk
        if (wid & 1) {     // warp-parity stagger
            DO_KSTEP(32)
            DO_PREFETCH()
            DO_KSTEP(0)
        } else {
            DO_KSTEP(0)
            DO_PREFETCH()
            DO_KSTEP(32)
        }
    }

    if (MODE == 0) {
        // scatter: Q -> fp16 pair; K,V -> fp16 single
        #pragma unroll
        for (int i = 0; i < 2; i++)
            #pragma unroll
            for (int n = 0; n < 8; n++)
                #pragma unroll
                for (int r = 0; r < 4; r++) {
                    int row = m0 + wm * 32 + i * 16 + (lane >> 2) + (r >> 1) * 8;
                    int col = n0 + wn * 64 + n * 8 + (lane & 3) * 2 + (r & 1);
                    float v = acc[i][n][r] + __ldg(bias + col);
                    int bb = row >> 11;
                    int tt = row & (Tv - 1);
                    int h  = col / 192;
                    int rr = col - h * 192;
                    size_t off = (((size_t)(bb * Hv + h)) * Tv + tt) * HDv + (rr & 63);
                    if (rr < 64) {
                        __half hi = __float2half_rn(v);
                        g_Qh[off] = hi;
                        g_Ql[off] = __float2half_rn(v - __half2float(hi));
                    } else if (rr < 128) {
                        g_Kh[off] = __float2half_rn(v);
                    } else {
                        g_Vh[off] = __float2half_rn(v);
                    }
                }
    } else {
        #pragma unroll
        for (int i = 0; i < 2; i++)
            #pragma unroll
            for (int n = 0; n < 8; n++) {
                int row = m0 + wm * 32 + i * 16 + (lane >> 2);
                int col = n0 + wn * 64 + n * 8 + (lane & 3) * 2;
                float b0 = __ldg(bias + col), b1 = __ldg(bias + col + 1);
                float2 v0 = make_float2(acc[i][n][0] + b0, acc[i][n][1] + b1);
                float2 v1 = make_float2(acc[i][n][2] + b0, acc[i][n][3] + b1);
                *reinterpret_cast<float2*>(C + (size_t)row * Dv + col)       = v0;
                *reinterpret_cast<float2*>(C + (size_t)(row + 8) * Dv + col) = v1;
            }
    }
}

// ---------------- flash attention: fp16 2-pass, 2 CTAs/SM (R14) -------------
#define FRS        72
#define FQ_TILE_B  (128 * FRS * 2)
#define FK_TILE_B  (64 * FRS * 2)
#define FST_B      (2 * FK_TILE_B)
#define FLASH_SMEM (2 * FQ_TILE_B + 2 * FST_B)

__global__ __launch_bounds__(256, 2) void flash_mma() {
    extern __shared__ __align__(1024) char fsm[];
    const uint32_t base = smem_u32(fsm);

    const int t    = threadIdx.x;
    const int lane = t & 31;
    const int wid  = t >> 5;
    const int bh   = blockIdx.y;
    const int qt   = (Tv / 128 - 1) - blockIdx.x;   // big tiles first
    const int q0   = qt * 128;
    const int NKT  = 2 * qt + 2;

    const __half* Qhg = g_Qh + ((size_t)bh * Tv + q0) * HDv;
    const __half* Qlg = g_Ql + ((size_t)bh * Tv + q0) * HDv;
    const __half* Khg = g_Kh + (size_t)bh * Tv * HDv;
    const __half* Vhg = g_Vh + (size_t)bh * Tv * HDv;

    #pragma unroll
    for (int i = 0; i < 4; i++) {
        int g = t + i * 256;
        int r = g >> 3;
        int c8 = (g & 7) * 8;
        uint32_t so = (uint32_t)(r * FRS + c8) * 2;
        cp16(base + so,             Qhg + r * HDv + c8);
        cp16(base + FQ_TILE_B + so, Qlg + r * HDv + c8);
    }
    CP_COMMIT();
    #pragma unroll
    for (int i = 0; i < 2; i++) {
        int g = t + i * 256;
        int r = g >> 3, c8 = (g & 7) * 8;
        uint32_t st = base + 2 * FQ_TILE_B;
        uint32_t so = (uint32_t)(r * FRS + c8) * 2;
        int go = r * HDv + c8;
        cp16(st + so,             Khg + go);
        cp16(st + FK_TILE_B + so, Vhg + go);
    }
    CP_COMMIT();

    const int qw0 = q0 + wid * 16;
    float m_[2] = {-INFINITY, -INFINITY};
    float l_[2] = {0.0f, 0.0f};
    float o[8][4];
    #pragma unroll
    for (int n = 0; n < 8; n++)
        #pragma unroll
        for (int e = 0; e < 4; e++) o[n][e] = 0.0f;

    const uint32_t q_lmb  = base + (uint32_t)((wid * 16 + (lane & 15)) * FRS + (lane >> 4) * 8) * 2;
    const uint32_t k_lane = (uint32_t)((lane & 15) * FRS + (lane >> 4) * 8) * 2;
    const uint32_t v_lane = (uint32_t)(((lane & 7) + ((lane >> 4) << 3)) * FRS + ((lane >> 3) & 1) * 8) * 2;

    for (int kt = 0; kt < NKT; kt++) {
        const uint32_t st = base + 2 * FQ_TILE_B + (uint32_t)(kt & 1) * FST_B;
        CP_WAIT_0();
        __syncthreads();
        if (kt + 1 < NKT) {
            const uint32_t st1 = base + 2 * FQ_TILE_B + (uint32_t)((kt + 1) & 1) * FST_B;
            const int kr = (kt + 1) * 64;
            #pragma unroll
            for (int i = 0; i < 2; i++) {
                int g = t + i * 256;
                int r = g >> 3, c8 = (g & 7) * 8;
                uint32_t so = (uint32_t)(r * FRS + c8) * 2;
                int go = (kr + r) * HDv + c8;
                cp16(st1 + so,             Khg + go);
                cp16(st1 + FK_TILE_B + so, Vhg + go);
            }
            CP_COMMIT();
        }

        const int k0 = kt * 64;
        if (k0 <= qw0 + 15) {
            float sa[8][4];
            #pragma unroll
            for (int n = 0; n < 8; n++)
                #pragma unroll
                for (int e = 0; e < 4; e++) sa[n][e] = 0.0f;

            #pragma unroll
            for (int kg = 0; kg < 4; kg++) {
                uint32_t qhf[4], qlf[4];
                ldm_x4(qhf, q_lmb + kg * 32);
                ldm_x4(qlf, q_lmb + FQ_TILE_B + kg * 32);
                uint32_t kb[4][4];
                #pragma unroll
                for (int np = 0; np < 4; np++)
                    ldm_x4(kb[np], st + k_lane + (uint32_t)(np * 16 * FRS * 2) + kg * 32);
                #pragma unroll
                for (int np = 0; np < 4; np++) {
                    mma_f16(sa[2*np],   qhf, kb[np][0], kb[np][2]);
                    mma_f16(sa[2*np+1], qhf, kb[np][1], kb[np][3]);
                }
                #pragma unroll
                for (int np = 0; np < 4; np++) {
                    mma_f16(sa[2*np],   qlf, kb[np][0], kb[np][2]);
                    mma_f16(sa[2*np+1], qlf, kb[np][1], kb[np][3]);
                }
            }

            const int r0 = qw0 + (lane >> 2);
            #pragma unroll
            for (int n = 0; n < 8; n++)
                #pragma unroll
                for (int e = 0; e < 4; e++) {
                    float v = sa[n][e] * 0.125f;
                    int rr = r0 + (e >> 1) * 8;
                    int cc = k0 + n * 8 + (lane & 3) * 2 + (e & 1);
                    sa[n][e] = (cc > rr) ? -INFINITY : v;
                }

            float corr[2];
            #pragma unroll
            for (int rh = 0; rh < 2; rh++) {
                float mx = -INFINITY;
                #pragma unroll
                for (int n = 0; n < 8; n++)
                    mx = fmaxf(mx, fmaxf(sa[n][2*rh], sa[n][2*rh+1]));
                mx = fmaxf(mx, __shfl_xor_sync(0xffffffffu, mx, 1));
                mx = fmaxf(mx, __shfl_xor_sync(0xffffffffu, mx, 2));
                float mnew = fmaxf(m_[rh], mx);
                corr[rh] = __expf(m_[rh] - mnew);
                m_[rh] = mnew;
                float rs = 0.0f;
                #pragma unroll
                for (int n = 0; n < 8; n++) {
                    float p0 = __expf(sa[n][2*rh]   - mnew);
                    float p1 = __expf(sa[n][2*rh+1] - mnew);
                    sa[n][2*rh] = p0; sa[n][2*rh+1] = p1;
                    rs += p0 + p1;
                }
                rs += __shfl_xor_sync(0xffffffffu, rs, 1);
                rs += __shfl_xor_sync(0xffffffffu, rs, 2);
                l_[rh] = l_[rh] * corr[rh] + rs;
            }
            #pragma unroll
            for (int n = 0; n < 8; n++) {
                o[n][0] *= corr[0]; o[n][1] *= corr[0];
                o[n][2] *= corr[1]; o[n][3] *= corr[1];
            }

            #pragma unroll
            for (int kg = 0; kg < 4; kg++) {
                uint32_t pah[4], pal[4];
                pack_hl_f16(sa[2*kg][0],   sa[2*kg][1],   pah[0], pal[0]);
                pack_hl_f16(sa[2*kg][2],   sa[2*kg][3],   pah[1], pal[1]);
                pack_hl_f16(sa[2*kg+1][0], sa[2*kg+1][1], pah[2], pal[2]);
                pack_hl_f16(sa[2*kg+1][2], sa[2*kg+1][3], pah[3], pal[3]);
                uint32_t vb[4][4];
                #pragma unroll
                for (int ndp = 0; ndp < 4; ndp++)
                    ldm_x4_t(vb[ndp], st + FK_TILE_B + v_lane
                                      + (uint32_t)(kg * 16 * FRS * 2) + ndp * 32);
                #pragma unroll
                for (int ndp = 0; ndp < 4; ndp++) {
                    mma_f16(o[2*ndp],   pah, vb[ndp][0], vb[ndp][2]);
                    mma_f16(o[2*ndp+1], pah, vb[ndp][1], vb[ndp][3]);
                }
                #pragma unroll
                for (int ndp = 0; ndp < 4; ndp++) {
                    mma_f16(o[2*ndp],   pal, vb[ndp][0], vb[ndp][2]);
                    mma_f16(o[2*ndp+1], pal, vb[ndp][1], vb[ndp][3]);
                }
            }
        }
    }

    const int bb = bh >> 4;
    const int h  = bh & 15;
    const float i0 = 1.0f / l_[0], i1 = 1.0f / l_[1];
    const int row = q0 + wid * 16 + (lane >> 2);
    const size_t base0 = ((size_t)(bb * Tv) + row) * Dv;
    const size_t base1 = base0 + (size_t)8 * Dv;
    #pragma unroll
    for (int nd = 0; nd < 8; nd++) {
        int col = h * 64 + nd * 8 + (lane & 3) * 2;
        uint32_t h0, l0, h1, l1;
        pack_hl_f16(o[nd][0] * i0, o[nd][1] * i0, h0, l0);
        pack_hl_f16(o[nd][2] * i1, o[nd][3] * i1, h1, l1);
        *reinterpret_cast<uint32_t*>(&g_ah[base0 + col]) = h0;
        *reinterpret_cast<uint32_t*>(&g_al[base0 + col]) = l0;
        *reinterpret_cast<uint32_t*>(&g_ah[base1 + col]) = h1;
        *reinterpret_cast<uint32_t*>(&g_al[base1 + col]) = l1;
    }
}

// ---------------------------------------------------------------------------
extern "C" void kernel_launch(void* const* d_in, const int* in_sizes, int n_in,
                              void* d_out, int out_size) {
    const float* x    = (const float*)d_in[0];
    const float* Wqkv = (const float*)d_in[1];
    const float* bqkv = (const float*)d_in[2];
    const float* Wout = (const float*)d_in[3];
    const float* bout = (const float*)d_in[4];
    float* out = (float*)d_out;

    void *xh, *xl, *wqh, *ah, *al, *woh;
    cudaGetSymbolAddress(&xh,  g_xh);  cudaGetSymbolAddress(&xl,  g_xl);
    cudaGetSymbolAddress(&wqh, g_wqh);
    cudaGetSymbolAddress(&ah,  g_ah);  cudaGetSymbolAddress(&al,  g_al);
    cudaGetSymbolAddress(&woh, g_woh);

    cudaFuncSetAttribute(gemm_f16,  cudaFuncAttributeMaxDynamicSharedMemorySize, 2 * STG_B);
    cudaFuncSetAttribute(flash_mma, cudaFuncAttributeMaxDynamicSharedMemorySize, FLASH_SMEM);

    // splits: x -> fp16 pair; Wqkv, Wout -> fp16 single
    split_all_kernel<<<(XN4 + WQN4 + WON4 + 255) / 256, 256>>>(
        x, Wqkv, Wout,
        (__half*)xh, (__half*)xl, (__half*)wqh, (__half*)woh);

    // 1) QKV projection (fp16 2-pass, 128x128 tile)
    gemm_f16<<<dim3(QKV_N / 128, Mv / 128), 256, 2 * STG_B>>>(
        (const __half*)xh, (const __half*)xl, (const __half*)wqh, bqkv, nullptr, 0);

    // 2) causal flash attention (fp16 2-pass, 2 CTAs/SM)
    flash_mma<<<dim3(Tv / 128, Bv * Hv), 256, FLASH_SMEM>>>();

    // 3) output projection (fp16 2-pass, 128x128 tile)
    gemm_f16<<<dim3(Dv / 128, Mv / 128), 256, 2 * STG_B>>>(
        (const __half*)ah, (const __half*)al, (const __half*)woh, bout, out, 1);
}

// round 16
// speedup vs baseline: 1.7443x; 1.2120x over previous
#include <cuda_runtime.h>
#include <cuda_fp16.h>
#include <math.h>
#include <stdint.h>

#define Bv 2
#define Tv 2048
#define Dv 1024
#define Hv 16
#define HDv 64
#define Mv 4096          // B*T
#define Kv 1024
#define QKV_N 3072

// ---------------- device scratch (no allocations allowed) ------------------
__device__ __align__(16) __half g_Qh[Bv*Hv*Tv*HDv];                       // fp16 single
__device__ __align__(16) __half g_Kh[Bv*Hv*Tv*HDv];                       // fp16 single
__device__ __align__(16) __half g_Vh[Bv*Hv*Tv*HDv];                       // fp16 single

__device__ __align__(16) __half g_xh[Mv*Kv], g_xl[Mv*Kv];                 // fp16 pair
__device__ __align__(16) __half g_wqh[QKV_N*Kv];                          // fp16 single
__device__ __align__(16) __half g_ah[Mv*Kv], g_al[Mv*Kv];                 // fp16 pair
__device__ __align__(16) __half g_woh[Dv*Kv];                             // fp16 single

// ---------------- PTX helpers ------------------------------------------------
__device__ __forceinline__ uint32_t smem_u32(const void* p) {
    uint32_t a;
    asm("{ .reg .u64 t; cvta.to.shared.u64 t, %1; cvt.u32.u64 %0, t; }" : "=r"(a) : "l"(p));
    return a;
}
__device__ __forceinline__ void cp16(uint32_t s, const void* g) {
    asm volatile("cp.async.cg.shared.global [%0], [%1], 16;" :: "r"(s), "l"(g));
}
#define CP_COMMIT()  asm volatile("cp.async.commit_group;" ::: "memory")
#define CP_WAIT_0()  asm volatile("cp.async.wait_group 0;" ::: "memory")

__device__ __forceinline__ void ldm_x4(uint32_t* r, uint32_t a) {
    asm volatile("ldmatrix.sync.aligned.m8n8.x4.shared.b16 {%0,%1,%2,%3}, [%4];"
        : "=r"(r[0]), "=r"(r[1]), "=r"(r[2]), "=r"(r[3]) : "r"(a));
}
__device__ __forceinline__ void ldm_x4_t(uint32_t* r, uint32_t a) {
    asm volatile("ldmatrix.sync.aligned.m8n8.x4.trans.shared.b16 {%0,%1,%2,%3}, [%4];"
        : "=r"(r[0]), "=r"(r[1]), "=r"(r[2]), "=r"(r[3]) : "r"(a));
}
__device__ __forceinline__ void mma_f16(float* d, const uint32_t* a,
                                        uint32_t b0, uint32_t b1) {
    asm volatile(
        "mma.sync.aligned.m16n8k16.row.col.f32.f16.f16.f32 "
        "{%0,%1,%2,%3}, {%4,%5,%6,%7}, {%8,%9}, {%0,%1,%2,%3};"
        : "+f"(d[0]), "+f"(d[1]), "+f"(d[2]), "+f"(d[3])
        : "r"(a[0]), "r"(a[1]), "r"(a[2]), "r"(a[3]), "r"(b0), "r"(b1));
}
__device__ __forceinline__ uint32_t pack_f16(float p0, float p1) {
    __half2 h = __floats2half2_rn(p0, p1);
    return *reinterpret_cast<uint32_t*>(&h);
}
__device__ __forceinline__ void pack_hl_f16(float p0, float p1, uint32_t& h, uint32_t& l) {
    __half h0 = __float2half_rn(p0), h1 = __float2half_rn(p1);
    h = (uint32_t)__half_as_ushort(h0) | ((uint32_t)__half_as_ushort(h1) << 16);
    __half l0 = __float2half_rn(p0 - __half2float(h0));
    __half l1 = __float2half_rn(p1 - __half2float(h1));
    l = (uint32_t)__half_as_ushort(l0) | ((uint32_t)__half_as_ushort(l1) << 16);
}

// ---------------- fused split: x -> fp16 pair; Wqkv,Wout -> fp16 single -----
#define XN4   (Mv * Kv / 4)
#define WQN4  (QKV_N * Kv / 4)
#define WON4  (Dv * Kv / 4)

__global__ __launch_bounds__(256) void split_all_kernel(const float* __restrict__ x,
                                                        const float* __restrict__ wq,
                                                        const float* __restrict__ wo,
                                                        __half* __restrict__ xh,
                                                        __half* __restrict__ xl,
                                                        __half* __restrict__ wqh,
                                                        __half* __restrict__ woh) {
    int i = blockIdx.x * blockDim.x + threadIdx.x;
    if (i >= XN4 + WQN4 + WON4) return;
    if (i < XN4) {
        float4 v = reinterpret_cast<const float4*>(x)[i];
        ushort4 h, l;
        __half b;
        b = __float2half_rn(v.x); h.x = __half_as_ushort(b);
        l.x = __half_as_ushort(__float2half_rn(v.x - __half2float(b)));
        b = __float2half_rn(v.y); h.y = __half_as_ushort(b);
        l.y = __half_as_ushort(__float2half_rn(v.y - __half2float(b)));
        b = __float2half_rn(v.z); h.z = __half_as_ushort(b);
        l.z = __half_as_ushort(__float2half_rn(v.z - __half2float(b)));
        b = __float2half_rn(v.w); h.w = __half_as_ushort(b);
        l.w = __half_as_ushort(__float2half_rn(v.w - __half2float(b)));
        reinterpret_cast<ushort4*>(xh)[i] = h;
        reinterpret_cast<ushort4*>(xl)[i] = l;
        return;
    }
    const float* s; __half* dst;
    if (i < XN4 + WQN4) { i -= XN4;        s = wq; dst = wqh; }
    else                { i -= XN4 + WQN4; s = wo; dst = woh; }
    float4 v = reinterpret_cast<const float4*>(s)[i];
    ushort4 h;
    h.x = __half_as_ushort(__float2half_rn(v.x));
    h.y = __half_as_ushort(__float2half_rn(v.y));
    h.z = __half_as_ushort(__float2half_rn(v.z));
    h.w = __half_as_ushort(__float2half_rn(v.w));
    reinterpret_cast<ushort4*>(dst)[i] = h;
}

// ---------------- unified fp16 2-pass GEMM: 128x128 tile, 2 CTAs/SM ---------
#define RS      40
#define TILE_A  (128 * RS * 2)          // 10240
#define STG_B   (3 * TILE_A)            // Ah + Al + Bh per stage

#define DO_KSTEP(KO) \
    { \
        uint32_t af[2][4], bf_[4][4]; \
        _Pragma("unroll") \
        for (int i = 0; i < 2; i++) \
            ldm_x4(af[i], a_base + s + (KO) + (uint32_t)i * (16 * RS * 2)); \
        _Pragma("unroll") \
        for (int j = 0; j < 4; j++) \
            ldm_x4(bf_[j], b_base + s + (KO) + (uint32_t)j * (16 * RS * 2)); \
        _Pragma("unroll") \
        for (int i = 0; i < 2; i++) \
            _Pragma("unroll") \
            for (int n = 0; n < 8; n++) \
                mma_f16(acc[i][n], af[i], bf_[n>>1][n&1], bf_[n>>1][2+(n&1)]); \
        uint32_t alf[2][4]; \
        _Pragma("unroll") \
        for (int i = 0; i < 2; i++) \
            ldm_x4(alf[i], a_base + s + (KO) + TILE_A + (uint32_t)i * (16 * RS * 2)); \
        _Pragma("unroll") \
        for (int i = 0; i < 2; i++) \
            _Pragma("unroll") \
            for (int n = 0; n < 8; n++) \
                mma_f16(acc[i][n], alf[i], bf_[n>>1][n&1], bf_[n>>1][2+(n&1)]); \
    }

#define DO_PREFETCH() \
    if (kt + 1 < NCHUNK) { \
        const uint32_t s1 = (uint32_t)((kt + 1) & 1) * STG_B; \
        const int k1 = (kt + 1) * 32; \
        _Pragma("unroll") \
        for (int i = 0; i < 2; i++) { \
            cp16(dsb + s1 + soffA[i],              Ahb + goffA[i] + k1); \
            cp16(dsb + s1 + TILE_A + soffA[i],     Alb + goffA[i] + k1); \
            cp16(dsb + s1 + 2u*TILE_A + soffA[i],  Bhb + goffA[i] + k1); \
        } \
        CP_COMMIT(); \
    }

__global__ __launch_bounds__(256, 2) void gemm_f16(const __half* __restrict__ Ah,
                                                   const __half* __restrict__ Al,
                                                   const __half* __restrict__ Bh,
                                                   const float* __restrict__ bias,
                                                   float* __restrict__ C, int MODE) {
    extern __shared__ __align__(1024) char dsm[];
    const uint32_t dsb = smem_u32(dsm);

    const int t    = threadIdx.x;
    const int lane = t & 31;
    const int wid  = t >> 5;
    const int wm   = wid & 3;
    const int wn   = wid >> 2;
    const int m0   = blockIdx.y * 128;
    const int n0   = blockIdx.x * 128;

    int goffA[2]; uint32_t soffA[2];
    #pragma unroll
    for (int i = 0; i < 2; i++) {
        int g   = t + i * 256;
        int row = g >> 2;
        int c8  = (g & 3) * 8;
        goffA[i] = row * Kv + c8;
        soffA[i] = (uint32_t)(row * RS + c8) * 2;
    }

    const __half* Ahb = Ah + (size_t)m0 * Kv;
    const __half* Alb = Al + (size_t)m0 * Kv;
    const __half* Bhb = Bh + (size_t)n0 * Kv;

    const uint32_t a_base = dsb + (uint32_t)((wm * 32 + (lane & 15)) * RS + (lane >> 4) * 8) * 2;
    const uint32_t b_base = dsb + 2u * TILE_A
                          + (uint32_t)((wn * 64 + (lane & 15)) * RS + (lane >> 4) * 8) * 2;

    float acc[2][8][4];
    #pragma unroll
    for (int i = 0; i < 2; i++)
        #pragma unroll
        for (int n = 0; n < 8; n++)
            #pragma unroll
            for (int r = 0; r < 4; r++) acc[i][n][r] = 0.0f;

    #pragma unroll
    for (int i = 0; i < 2; i++) {
        cp16(dsb + soffA[i],              Ahb + goffA[i]);
        cp16(dsb + TILE_A + soffA[i],     Alb + goffA[i]);
        cp16(dsb + 2u*TILE_A + soffA[i],  Bhb + goffA[i]);
    }
    CP_COMMIT();

    const int NCHUNK = Kv / 32;
    for (int kt = 0; kt < NCHUNK; kt++) {
        const uint32_t s = (uint32_t)(kt & 1) * STG_B;
        CP_WAIT_0();
        __syncthreads();
        if (wid & 1) {
            DO_KSTEP(32)
            DO_PREFETCH()
            DO_KSTEP(0)
        } else {
            DO_KSTEP(0)
            DO_PREFETCH()
            DO_KSTEP(32)
        }
    }

    if (MODE == 0) {
        // scatter: Q, K, V all fp16 single
        #pragma unroll
        for (int i = 0; i < 2; i++)
            #pragma unroll
            for (int n = 0; n < 8; n++)
                #pragma unroll
                for (int r = 0; r < 4; r++) {
                    int row = m0 + wm * 32 + i * 16 + (lane >> 2) + (r >> 1) * 8;
                    int col = n0 + wn * 64 + n * 8 + (lane & 3) * 2 + (r & 1);
                    float v = acc[i][n][r] + __ldg(bias + col);
                    int bb = row >> 11;
                    int tt = row & (Tv - 1);
                    int h  = col / 192;
                    int rr = col - h * 192;
                    size_t off = (((size_t)(bb * Hv + h)) * Tv + tt) * HDv + (rr & 63);
                    __half hv = __float2half_rn(v);
                    if (rr < 64)       g_Qh[off] = hv;
                    else if (rr < 128) g_Kh[off] = hv;
                    else               g_Vh[off] = hv;
                }
    } else {
        #pragma unroll
        for (int i = 0; i < 2; i++)
            #pragma unroll
            for (int n = 0; n < 8; n++) {
                int row = m0 + wm * 32 + i * 16 + (lane >> 2);
                int col = n0 + wn * 64 + n * 8 + (lane & 3) * 2;
                float b0 = __ldg(bias + col), b1 = __ldg(bias + col + 1);
                float2 v0 = make_float2(acc[i][n][0] + b0, acc[i][n][1] + b1);
                float2 v1 = make_float2(acc[i][n][2] + b0, acc[i][n][3] + b1);
                *reinterpret_cast<float2*>(C + (size_t)row * Dv + col)       = v0;
                *reinterpret_cast<float2*>(C + (size_t)(row + 8) * Dv + col) = v1;
            }
    }
}

// ---------------- flash attention: fp16 single-pass S and PV ----------------
#define FRS        72
#define FQ_TILE_B  (128 * FRS * 2)          // 18432 (Q single)
#define FK_TILE_B  (64 * FRS * 2)           // 9216
#define FST_B      (2 * FK_TILE_B)          // 18432 (Kh, Vh)
#define FLASH_SMEM (FQ_TILE_B + 2 * FST_B)  // 55296

__global__ __launch_bounds__(256, 2) void flash_mma() {
    extern __shared__ __align__(1024) char fsm[];
    const uint32_t base = smem_u32(fsm);

    const int t    = threadIdx.x;
    const int lane = t & 31;
    const int wid  = t >> 5;
    const int bh   = blockIdx.y;
    const int qt   = (Tv / 128 - 1) - blockIdx.x;   // big tiles first
    const int q0   = qt * 128;
    const int NKT  = 2 * qt + 2;

    const __half* Qhg = g_Qh + ((size_t)bh * Tv + q0) * HDv;
    const __half* Khg = g_Kh + (size_t)bh * Tv * HDv;
    const __half* Vhg = g_Vh + (size_t)bh * Tv * HDv;

    // Q tile (single)
    #pragma unroll
    for (int i = 0; i < 4; i++) {
        int g = t + i * 256;
        int r = g >> 3;
        int c8 = (g & 7) * 8;
        cp16(base + (uint32_t)(r * FRS + c8) * 2, Qhg + r * HDv + c8);
    }
    CP_COMMIT();
    // stage 0 K,V
    #pragma unroll
    for (int i = 0; i < 2; i++) {
        int g = t + i * 256;
        int r = g >> 3, c8 = (g & 7) * 8;
        uint32_t st = base + FQ_TILE_B;
        uint32_t so = (uint32_t)(r * FRS + c8) * 2;
        int go = r * HDv + c8;
        cp16(st + so,             Khg + go);
        cp16(st + FK_TILE_B + so, Vhg + go);
    }
    CP_COMMIT();

    const int qw0 = q0 + wid * 16;
    float m_[2] = {-INFINITY, -INFINITY};
    float l_[2] = {0.0f, 0.0f};
    float o[8][4];
    #pragma unroll
    for (int n = 0; n < 8; n++)
        #pragma unroll
        for (int e = 0; e < 4; e++) o[n][e] = 0.0f;

    const uint32_t q_lmb  = base + (uint32_t)((wid * 16 + (lane & 15)) * FRS + (lane >> 4) * 8) * 2;
    const uint32_t k_lane = (uint32_t)((lane & 15) * FRS + (lane >> 4) * 8) * 2;
    const uint32_t v_lane = (uint32_t)(((lane & 7) + ((lane >> 4) << 3)) * FRS + ((lane >> 3) & 1) * 8) * 2;

    // Q fragments persistent (only 16 regs now)
    uint32_t qf[4][4];
    bool qloaded = false;

    for (int kt = 0; kt < NKT; kt++) {
        const uint32_t st = base + FQ_TILE_B + (uint32_t)(kt & 1) * FST_B;
        CP_WAIT_0();
        __syncthreads();
        if (kt + 1 < NKT) {
            const uint32_t st1 = base + FQ_TILE_B + (uint32_t)((kt + 1) & 1) * FST_B;
            const int kr = (kt + 1) * 64;
            #pragma unroll
            for (int i = 0; i < 2; i++) {
                int g = t + i * 256;
                int r = g >> 3, c8 = (g & 7) * 8;
                uint32_t so = (uint32_t)(r * FRS + c8) * 2;
                int go = (kr + r) * HDv + c8;
                cp16(st1 + so,             Khg + go);
                cp16(st1 + FK_TILE_B + so, Vhg + go);
            }
            CP_COMMIT();
        }

        if (!qloaded) {
            #pragma unroll
            for (int kg = 0; kg < 4; kg++)
                ldm_x4(qf[kg], q_lmb + kg * 32);
            qloaded = true;
        }

        const int k0 = kt * 64;
        if (k0 <= qw0 + 15) {
            // ---- S = Q Kh^T (single pass) ----
            float sa[8][4];
            #pragma unroll
            for (int n = 0; n < 8; n++)
                #pragma unroll
                for (int e = 0; e < 4; e++) sa[n][e] = 0.0f;

            #pragma unroll
            for (int kg = 0; kg < 4; kg++) {
                uint32_t kb[4][4];
                #pragma unroll
                for (int np = 0; np < 4; np++)
                    ldm_x4(kb[np], st + k_lane + (uint32_t)(np * 16 * FRS * 2) + kg * 32);
                #pragma unroll
                for (int np = 0; np < 4; np++) {
                    mma_f16(sa[2*np],   qf[kg], kb[np][0], kb[np][2]);
                    mma_f16(sa[2*np+1], qf[kg], kb[np][1], kb[np][3]);
                }
            }

            // ---- scale + causal mask ----
            const int r0 = qw0 + (lane >> 2);
            #pragma unroll
            for (int n = 0; n < 8; n++)
                #pragma unroll
                for (int e = 0; e < 4; e++) {
                    float v = sa[n][e] * 0.125f;
                    int rr = r0 + (e >> 1) * 8;
                    int cc = k0 + n * 8 + (lane & 3) * 2 + (e & 1);
                    sa[n][e] = (cc > rr) ? -INFINITY : v;
                }

            // ---- online softmax ----
            float corr[2];
            #pragma unroll
            for (int rh = 0; rh < 2; rh++) {
                float mx = -INFINITY;
                #pragma unroll
                for (int n = 0; n < 8; n++)
                    mx = fmaxf(mx, fmaxf(sa[n][2*rh], sa[n][2*rh+1]));
                mx = fmaxf(mx, __shfl_xor_sync(0xffffffffu, mx, 1));
                mx = fmaxf(mx, __shfl_xor_sync(0xffffffffu, mx, 2));
                float mnew = fmaxf(m_[rh], mx);
                corr[rh] = __expf(m_[rh] - mnew);
                m_[rh] = mnew;
                float rs = 0.0f;
                #pragma unroll
                for (int n = 0; n < 8; n++) {
                    float p0 = __expf(sa[n][2*rh]   - mnew);
                    float p1 = __expf(sa[n][2*rh+1] - mnew);
                    sa[n][2*rh] = p0; sa[n][2*rh+1] = p1;
                    rs += p0 + p1;
                }
                rs += __shfl_xor_sync(0xffffffffu, rs, 1);
                rs += __shfl_xor_sync(0xffffffffu, rs, 2);
                l_[rh] = l_[rh] * corr[rh] + rs;
            }
            #pragma unroll
            for (int n = 0; n < 8; n++) {
                o[n][0] *= corr[0]; o[n][1] *= corr[0];
                o[n][2] *= corr[1]; o[n][3] *= corr[1];
            }

            // ---- O += P Vh (single pass, P fp16) ----
            #pragma unroll
            for (int kg = 0; kg < 4; kg++) {
                uint32_t pa[4];
                pa[0] = pack_f16(sa[2*kg][0],   sa[2*kg][1]);
                pa[1] = pack_f16(sa[2*kg][2],   sa[2*kg][3]);
                pa[2] = pack_f16(sa[2*kg+1][0], sa[2*kg+1][1]);
                pa[3] = pack_f16(sa[2*kg+1][2], sa[2*kg+1][3]);
                uint32_t vb[4][4];
                #pragma unroll
                for (int ndp = 0; ndp < 4; ndp++)
                    ldm_x4_t(vb[ndp], st + FK_TILE_B + v_lane
                                      + (uint32_t)(kg * 16 * FRS * 2) + ndp * 32);
                #pragma unroll
                for (int ndp = 0; ndp < 4; ndp++) {
                    mma_f16(o[2*ndp],   pa, vb[ndp][0], vb[ndp][2]);
                    mma_f16(o[2*ndp+1], pa, vb[ndp][1], vb[ndp][3]);
                }
            }
        }
    }

    // ---- finalize: write fp16 hi/lo attention output ----
    const int bb = bh >> 4;
    const int h  = bh & 15;
    const float i0 = 1.0f / l_[0], i1 = 1.0f / l_[1];
    const int row = q0 + wid * 16 + (lane >> 2);
    const size_t base0 = ((size_t)(bb * Tv) + row) * Dv;
    const size_t base1 = base0 + (size_t)8 * Dv;
    #pragma unroll
    for (int nd = 0; nd < 8; nd++) {
        int col = h * 64 + nd * 8 + (lane & 3) * 2;
        uint32_t h0, l0, h1, l1;
        pack_hl_f16(o[nd][0] * i0, o[nd][1] * i0, h0, l0);
        pack_hl_f16(o[nd][2] * i1, o[nd][3] * i1, h1, l1);
        *reinterpret_cast<uint32_t*>(&g_ah[base0 + col]) = h0;
        *reinterpret_cast<uint32_t*>(&g_al[base0 + col]) = l0;
        *reinterpret_cast<uint32_t*>(&g_ah[base1 + col]) = h1;
        *reinterpret_cast<uint32_t*>(&g_al[base1 + col]) = l1;
    }
}

// ---------------------------------------------------------------------------
extern "C" void kernel_launch(void* const* d_in, const int* in_sizes, int n_in,
                              void* d_out, int out_size) {
    const float* x    = (const float*)d_in[0];
    const float* Wqkv = (const float*)d_in[1];
    const float* bqkv = (const float*)d_in[2];
    const float* Wout = (const float*)d_in[3];
    const float* bout = (const float*)d_in[4];
    float* out = (float*)d_out;

    void *xh, *xl, *wqh, *ah, *al, *woh;
    cudaGetSymbolAddress(&xh,  g_xh);  cudaGetSymbolAddress(&xl,  g_xl);
    cudaGetSymbolAddress(&wqh, g_wqh);
    cudaGetSymbolAddress(&ah,  g_ah);  cudaGetSymbolAddress(&al,  g_al);
    cudaGetSymbolAddress(&woh, g_woh);

    cudaFuncSetAttribute(gemm_f16,  cudaFuncAttributeMaxDynamicSharedMemorySize, 2 * STG_B);
    cudaFuncSetAttribute(flash_mma, cudaFuncAttributeMaxDynamicSharedMemorySize, FLASH_SMEM);

    // splits: x -> fp16 pair; Wqkv, Wout -> fp16 single
    split_all_kernel<<<(XN4 + WQN4 + WON4 + 255) / 256, 256>>>(
        x, Wqkv, Wout,
        (__half*)xh, (__half*)xl, (__half*)wqh, (__half*)woh);

    // 1) QKV projection (fp16 2-pass, 128x128 tile) -> fp16 Q,K,V singles
    gemm_f16<<<dim3(QKV_N / 128, Mv / 128), 256, 2 * STG_B>>>(
        (const __half*)xh, (const __half*)xl, (const __half*)wqh, bqkv, nullptr, 0);

    // 2) causal flash attention (fp16 single-pass S and PV)
    flash_mma<<<dim3(Tv / 128, Bv * Hv), 256, FLASH_SMEM>>>();

    // 3) output projection (fp16 2-pass, 128x128 tile)
    gemm_f16<<<dim3(Dv / 128, Mv / 128), 256, 2 * STG_B>>>(
        (const __half*)ah, (const __half*)al, (const __half*)woh, bout, out, 1);
}

// round 17
// speedup vs baseline: 2.4182x; 1.3863x over previous
#include <cuda_runtime.h>
#include <cuda_fp16.h>
#include <math.h>
#include <stdint.h>

#define Bv 2
#define Tv 2048
#define Dv 1024
#define Hv 16
#define HDv 64
#define Mv 4096          // B*T
#define Kv 1024
#define QKV_N 3072

// ---------------- device scratch (no allocations allowed) ------------------
__device__ __align__(16) __half g_Qh[Bv*Hv*Tv*HDv];     // fp16 single
__device__ __align__(16) __half g_Kh[Bv*Hv*Tv*HDv];     // fp16 single
__device__ __align__(16) __half g_Vh[Bv*Hv*Tv*HDv];     // fp16 single

__device__ __align__(16) __half g_xh[Mv*Kv];            // fp16 single
__device__ __align__(16) __half g_wqh[QKV_N*Kv];        // fp16 single
__device__ __align__(16) __half g_ah[Mv*Kv];            // fp16 single (attn out)
__device__ __align__(16) __half g_woh[Dv*Kv];           // fp16 single

// ---------------- PTX helpers ------------------------------------------------
__device__ __forceinline__ uint32_t smem_u32(const void* p) {
    uint32_t a;
    asm("{ .reg .u64 t; cvta.to.shared.u64 t, %1; cvt.u32.u64 %0, t; }" : "=r"(a) : "l"(p));
    return a;
}
__device__ __forceinline__ void cp16(uint32_t s, const void* g) {
    asm volatile("cp.async.cg.shared.global [%0], [%1], 16;" :: "r"(s), "l"(g));
}
#define CP_COMMIT()  asm volatile("cp.async.commit_group;" ::: "memory")
#define CP_WAIT_0()  asm volatile("cp.async.wait_group 0;" ::: "memory")

__device__ __forceinline__ void ldm_x4(uint32_t* r, uint32_t a) {
    asm volatile("ldmatrix.sync.aligned.m8n8.x4.shared.b16 {%0,%1,%2,%3}, [%4];"
        : "=r"(r[0]), "=r"(r[1]), "=r"(r[2]), "=r"(r[3]) : "r"(a));
}
__device__ __forceinline__ void ldm_x4_t(uint32_t* r, uint32_t a) {
    asm volatile("ldmatrix.sync.aligned.m8n8.x4.trans.shared.b16 {%0,%1,%2,%3}, [%4];"
        : "=r"(r[0]), "=r"(r[1]), "=r"(r[2]), "=r"(r[3]) : "r"(a));
}
__device__ __forceinline__ void mma_f16(float* d, const uint32_t* a,
                                        uint32_t b0, uint32_t b1) {
    asm volatile(
        "mma.sync.aligned.m16n8k16.row.col.f32.f16.f16.f32 "
        "{%0,%1,%2,%3}, {%4,%5,%6,%7}, {%8,%9}, {%0,%1,%2,%3};"
        : "+f"(d[0]), "+f"(d[1]), "+f"(d[2]), "+f"(d[3])
        : "r"(a[0]), "r"(a[1]), "r"(a[2]), "r"(a[3]), "r"(b0), "r"(b1));
}
__device__ __forceinline__ uint32_t pack_f16(float p0, float p1) {
    __half2 h = __floats2half2_rn(p0, p1);
    return *reinterpret_cast<uint32_t*>(&h);
}

// ---------------- fused split: all three tensors -> fp16 single -------------
#define XN4   (Mv * Kv / 4)
#define WQN4  (QKV_N * Kv / 4)
#define WON4  (Dv * Kv / 4)

__global__ __launch_bounds__(256) void split_all_kernel(const float* __restrict__ x,
                                                        const float* __restrict__ wq,
                                                        const float* __restrict__ wo,
                                                        __half* __restrict__ xh,
                                                        __half* __restrict__ wqh,
                                                        __half* __restrict__ woh) {
    int i = blockIdx.x * blockDim.x + threadIdx.x;
    if (i >= XN4 + WQN4 + WON4) return;
    const float* s; __half* dst;
    if (i < XN4)             { s = x;  dst = xh; }
    else if (i < XN4 + WQN4) { i -= XN4;        s = wq; dst = wqh; }
    else                     { i -= XN4 + WQN4; s = wo; dst = woh; }
    float4 v = reinterpret_cast<const float4*>(s)[i];
    ushort4 h;
    h.x = __half_as_ushort(__float2half_rn(v.x));
    h.y = __half_as_ushort(__float2half_rn(v.y));
    h.z = __half_as_ushort(__float2half_rn(v.z));
    h.w = __half_as_ushort(__float2half_rn(v.w));
    reinterpret_cast<ushort4*>(dst)[i] = h;
}

// ---------------- fp16 1-pass GEMM: 128x128 tile, 2 CTAs/SM -----------------
// 8 warps, warp tile 32x64 (wm=wid&3, wn=wid>>2). BK=32.
// Per k16 step: 6 LDSM : 16 MMA.
// MODE 0: scatter Q/K/V fp16 single; MODE 1: fp32 C + bias.
#define RS      40
#define TILE_A  (128 * RS * 2)          // 10240 (A and B tiles both 128 rows)
#define STG_B   (2 * TILE_A)            // A + B = 20480 per stage

#define DO_KSTEP(KO) \
    { \
        uint32_t af[2][4], bf_[4][4]; \
        _Pragma("unroll") \
        for (int i = 0; i < 2; i++) \
            ldm_x4(af[i], a_base + s + (KO) + (uint32_t)i * (16 * RS * 2)); \
        _Pragma("unroll") \
        for (int j = 0; j < 4; j++) \
            ldm_x4(bf_[j], b_base + s + (KO) + (uint32_t)j * (16 * RS * 2)); \
        _Pragma("unroll") \
        for (int i = 0; i < 2; i++) \
            _Pragma("unroll") \
            for (int n = 0; n < 8; n++) \
                mma_f16(acc[i][n], af[i], bf_[n>>1][n&1], bf_[n>>1][2+(n&1)]); \
    }

#define DO_PREFETCH() \
    if (kt + 1 < NCHUNK) { \
        const uint32_t s1 = (uint32_t)((kt + 1) & 1) * STG_B; \
        const int k1 = (kt + 1) * 32; \
        _Pragma("unroll") \
        for (int i = 0; i < 2; i++) { \
            cp16(dsb + s1 + soffA[i],           Ahb + goffA[i] + k1); \
            cp16(dsb + s1 + TILE_A + soffA[i],  Bhb + goffA[i] + k1); \
        } \
        CP_COMMIT(); \
    }

__global__ __launch_bounds__(256, 2) void gemm_f16(const __half* __restrict__ Ah,
                                                   const __half* __restrict__ Bh,
                                                   const float* __restrict__ bias,
                                                   float* __restrict__ C, int MODE) {
    extern __shared__ __align__(1024) char dsm[];
    const uint32_t dsb = smem_u32(dsm);

    const int t    = threadIdx.x;
    const int lane = t & 31;
    const int wid  = t >> 5;
    const int wm   = wid & 3;        // 0..3 -> 32-row slices
    const int wn   = wid >> 2;       // 0..1 -> 64-col slices
    const int m0   = blockIdx.y * 128;
    const int n0   = blockIdx.x * 128;

    int goffA[2]; uint32_t soffA[2];
    #pragma unroll
    for (int i = 0; i < 2; i++) {
        int g   = t + i * 256;
        int row = g >> 2;
        int c8  = (g & 3) * 8;
        goffA[i] = row * Kv + c8;
        soffA[i] = (uint32_t)(row * RS + c8) * 2;
    }

    const __half* Ahb = Ah + (size_t)m0 * Kv;
    const __half* Bhb = Bh + (size_t)n0 * Kv;

    const uint32_t a_base = dsb + (uint32_t)((wm * 32 + (lane & 15)) * RS + (lane >> 4) * 8) * 2;
    const uint32_t b_base = dsb + (uint32_t)TILE_A
                          + (uint32_t)((wn * 64 + (lane & 15)) * RS + (lane >> 4) * 8) * 2;

    float acc[2][8][4];
    #pragma unroll
    for (int i = 0; i < 2; i++)
        #pragma unroll
        for (int n = 0; n < 8; n++)
            #pragma unroll
            for (int r = 0; r < 4; r++) acc[i][n][r] = 0.0f;

    #pragma unroll
    for (int i = 0; i < 2; i++) {
        cp16(dsb + soffA[i],          Ahb + goffA[i]);
        cp16(dsb + TILE_A + soffA[i], Bhb + goffA[i]);
    }
    CP_COMMIT();

    const int NCHUNK = Kv / 32;
    for (int kt = 0; kt < NCHUNK; kt++) {
        const uint32_t s = (uint32_t)(kt & 1) * STG_B;
        CP_WAIT_0();
        __syncthreads();   // single barrier per chunk
        if (wid & 1) {     // warp-parity stagger
            DO_KSTEP(32)
            DO_PREFETCH()
            DO_KSTEP(0)
        } else {
            DO_KSTEP(0)
            DO_PREFETCH()
            DO_KSTEP(32)
        }
    }

    if (MODE == 0) {
        // scatter: Q, K, V fp16 single
        #pragma unroll
        for (int i = 0; i < 2; i++)
            #pragma unroll
            for (int n = 0; n < 8; n++)
                #pragma unroll
                for (int r = 0; r < 4; r++) {
                    int row = m0 + wm * 32 + i * 16 + (lane >> 2) + (r >> 1) * 8;
                    int col = n0 + wn * 64 + n * 8 + (lane & 3) * 2 + (r & 1);
                    float v = acc[i][n][r] + __ldg(bias + col);
                    int bb = row >> 11;
                    int tt = row & (Tv - 1);
                    int h  = col / 192;
                    int rr = col - h * 192;
                    size_t off = (((size_t)(bb * Hv + h)) * Tv + tt) * HDv + (rr & 63);
                    __half hv = __float2half_rn(v);
                    if (rr < 64)       g_Qh[off] = hv;
                    else if (rr < 128) g_Kh[off] = hv;
                    else               g_Vh[off] = hv;
                }
    } else {
        #pragma unroll
        for (int i = 0; i < 2; i++)
            #pragma unroll
            for (int n = 0; n < 8; n++) {
                int row = m0 + wm * 32 + i * 16 + (lane >> 2);
                int col = n0 + wn * 64 + n * 8 + (lane & 3) * 2;
                float b0 = __ldg(bias + col), b1 = __ldg(bias + col + 1);
                float2 v0 = make_float2(acc[i][n][0] + b0, acc[i][n][1] + b1);
                float2 v1 = make_float2(acc[i][n][2] + b0, acc[i][n][3] + b1);
                *reinterpret_cast<float2*>(C + (size_t)row * Dv + col)       = v0;
                *reinterpret_cast<float2*>(C + (size_t)(row + 8) * Dv + col) = v1;
            }
    }
}

// ---------------- flash attention: fp16 single-pass S and PV (R16) ----------
#define FRS        72
#define FQ_TILE_B  (128 * FRS * 2)          // 18432 (Q single)
#define FK_TILE_B  (64 * FRS * 2)           // 9216
#define FST_B      (2 * FK_TILE_B)          // 18432 (Kh, Vh)
#define FLASH_SMEM (FQ_TILE_B + 2 * FST_B)  // 55296

__global__ __launch_bounds__(256, 2) void flash_mma() {
    extern __shared__ __align__(1024) char fsm[];
    const uint32_t base = smem_u32(fsm);

    const int t    = threadIdx.x;
    const int lane = t & 31;
    const int wid  = t >> 5;
    const int bh   = blockIdx.y;
    const int qt   = (Tv / 128 - 1) - blockIdx.x;   // big tiles first
    const int q0   = qt * 128;
    const int NKT  = 2 * qt + 2;

    const __half* Qhg = g_Qh + ((size_t)bh * Tv + q0) * HDv;
    const __half* Khg = g_Kh + (size_t)bh * Tv * HDv;
    const __half* Vhg = g_Vh + (size_t)bh * Tv * HDv;

    #pragma unroll
    for (int i = 0; i < 4; i++) {
        int g = t + i * 256;
        int r = g >> 3;
        int c8 = (g & 7) * 8;
        cp16(base + (uint32_t)(r * FRS + c8) * 2, Qhg + r * HDv + c8);
    }
    CP_COMMIT();
    #pragma unroll
    for (int i = 0; i < 2; i++) {
        int g = t + i * 256;
        int r = g >> 3, c8 = (g & 7) * 8;
        uint32_t st = base + FQ_TILE_B;
        uint32_t so = (uint32_t)(r * FRS + c8) * 2;
        int go = r * HDv + c8;
        cp16(st + so,             Khg + go);
        cp16(st + FK_TILE_B + so, Vhg + go);
    }
    CP_COMMIT();

    const int qw0 = q0 + wid * 16;
    float m_[2] = {-INFINITY, -INFINITY};
    float l_[2] = {0.0f, 0.0f};
    float o[8][4];
    #pragma unroll
    for (int n = 0; n < 8; n++)
        #pragma unroll
        for (int e = 0; e < 4; e++) o[n][e] = 0.0f;

    const uint32_t q_lmb  = base + (uint32_t)((wid * 16 + (lane & 15)) * FRS + (lane >> 4) * 8) * 2;
    const uint32_t k_lane = (uint32_t)((lane & 15) * FRS + (lane >> 4) * 8) * 2;
    const uint32_t v_lane = (uint32_t)(((lane & 7) + ((lane >> 4) << 3)) * FRS + ((lane >> 3) & 1) * 8) * 2;

    uint32_t qf[4][4];
    bool qloaded = false;

    for (int kt = 0; kt < NKT; kt++) {
        const uint32_t st = base + FQ_TILE_B + (uint32_t)(kt & 1) * FST_B;
        CP_WAIT_0();
        __syncthreads();
        if (kt + 1 < NKT) {
            const uint32_t st1 = base + FQ_TILE_B + (uint32_t)((kt + 1) & 1) * FST_B;
            const int kr = (kt + 1) * 64;
            #pragma unroll
            for (int i = 0; i < 2; i++) {
                int g = t + i * 256;
                int r = g >> 3, c8 = (g & 7) * 8;
                uint32_t so = (uint32_t)(r * FRS + c8) * 2;
                int go = (kr + r) * HDv + c8;
                cp16(st1 + so,             Khg + go);
                cp16(st1 + FK_TILE_B + so, Vhg + go);
            }
            CP_COMMIT();
        }

        if (!qloaded) {
            #pragma unroll
            for (int kg = 0; kg < 4; kg++)
                ldm_x4(qf[kg], q_lmb + kg * 32);
            qloaded = true;
        }

        const int k0 = kt * 64;
        if (k0 <= qw0 + 15) {
            float sa[8][4];
            #pragma unroll
            for (int n = 0; n < 8; n++)
                #pragma unroll
                for (int e = 0; e < 4; e++) sa[n][e] = 0.0f;

            #pragma unroll
            for (int kg = 0; kg < 4; kg++) {
                uint32_t kb[4][4];
                #pragma unroll
                for (int np = 0; np < 4; np++)
                    ldm_x4(kb[np], st + k_lane + (uint32_t)(np * 16 * FRS * 2) + kg * 32);
                #pragma unroll
                for (int np = 0; np < 4; np++) {
                    mma_f16(sa[2*np],   qf[kg], kb[np][0], kb[np][2]);
                    mma_f16(sa[2*np+1], qf[kg], kb[np][1], kb[np][3]);
                }
            }

            const int r0 = qw0 + (lane >> 2);
            #pragma unroll
            for (int n = 0; n < 8; n++)
                #pragma unroll
                for (int e = 0; e < 4; e++) {
                    float v = sa[n][e] * 0.125f;
                    int rr = r0 + (e >> 1) * 8;
                    int cc = k0 + n * 8 + (lane & 3) * 2 + (e & 1);
                    sa[n][e] = (cc > rr) ? -INFINITY : v;
                }

            float corr[2];
            #pragma unroll
            for (int rh = 0; rh < 2; rh++) {
                float mx = -INFINITY;
                #pragma unroll
                for (int n = 0; n < 8; n++)
                    mx = fmaxf(mx, fmaxf(sa[n][2*rh], sa[n][2*rh+1]));
                mx = fmaxf(mx, __shfl_xor_sync(0xffffffffu, mx, 1));
                mx = fmaxf(mx, __shfl_xor_sync(0xffffffffu, mx, 2));
                float mnew = fmaxf(m_[rh], mx);
                corr[rh] = __expf(m_[rh] - mnew);
                m_[rh] = mnew;
                float rs = 0.0f;
                #pragma unroll
                for (int n = 0; n < 8; n++) {
                    float p0 = __expf(sa[n][2*rh]   - mnew);
                    float p1 = __expf(sa[n][2*rh+1] - mnew);
                    sa[n][2*rh] = p0; sa[n][2*rh+1] = p1;
                    rs += p0 + p1;
                }
                rs += __shfl_xor_sync(0xffffffffu, rs, 1);
                rs += __shfl_xor_sync(0xffffffffu, rs, 2);
                l_[rh] = l_[rh] * corr[rh] + rs;
            }
            #pragma unroll
            for (int n = 0; n < 8; n++) {
                o[n][0] *= corr[0]; o[n][1] *= corr[0];
                o[n][2] *= corr[1]; o[n][3] *= corr[1];
            }

            #pragma unroll
            for (int kg = 0; kg < 4; kg++) {
                uint32_t pa[4];
                pa[0] = pack_f16(sa[2*kg][0],   sa[2*kg][1]);
                pa[1] = pack_f16(sa[2*kg][2],   sa[2*kg][3]);
                pa[2] = pack_f16(sa[2*kg+1][0], sa[2*kg+1][1]);
                pa[3] = pack_f16(sa[2*kg+1][2], sa[2*kg+1][3]);
                uint32_t vb[4][4];
                #pragma unroll
                for (int ndp = 0; ndp < 4; ndp++)
                    ldm_x4_t(vb[ndp], st + FK_TILE_B + v_lane
                                      + (uint32_t)(kg * 16 * FRS * 2) + ndp * 32);
                #pragma unroll
                for (int ndp = 0; ndp < 4; ndp++) {
                    mma_f16(o[2*ndp],   pa, vb[ndp][0], vb[ndp][2]);
                    mma_f16(o[2*ndp+1], pa, vb[ndp][1], vb[ndp][3]);
                }
            }
        }
    }

    // ---- finalize: write fp16 single attention output ----
    const int bb = bh >> 4;
    const int h  = bh & 15;
    const float i0 = 1.0f / l_[0], i1 = 1.0f / l_[1];
    const int row = q0 + wid * 16 + (lane >> 2);
    const size_t base0 = ((size_t)(bb * Tv) + row) * Dv;
    const size_t base1 = base0 + (size_t)8 * Dv;
    #pragma unroll
    for (int nd = 0; nd < 8; nd++) {
        int col = h * 64 + nd * 8 + (lane & 3) * 2;
        *reinterpret_cast<uint32_t*>(&g_ah[base0 + col]) = pack_f16(o[nd][0] * i0, o[nd][1] * i0);
        *reinterpret_cast<uint32_t*>(&g_ah[base1 + col]) = pack_f16(o[nd][2] * i1, o[nd][3] * i1);
    }
}

// ---------------------------------------------------------------------------
extern "C" void kernel_launch(void* const* d_in, const int* in_sizes, int n_in,
                              void* d_out, int out_size) {
    const float* x    = (const float*)d_in[0];
    const float* Wqkv = (const float*)d_in[1];
    const float* bqkv = (const float*)d_in[2];
    const float* Wout = (const float*)d_in[3];
    const float* bout = (const float*)d_in[4];
    float* out = (float*)d_out;

    void *xh, *wqh, *ah, *woh;
    cudaGetSymbolAddress(&xh,  g_xh);
    cudaGetSymbolAddress(&wqh, g_wqh);
    cudaGetSymbolAddress(&ah,  g_ah);
    cudaGetSymbolAddress(&woh, g_woh);

    cudaFuncSetAttribute(gemm_f16,  cudaFuncAttributeMaxDynamicSharedMemorySize, 2 * STG_B);
    cudaFuncSetAttribute(flash_mma, cudaFuncAttributeMaxDynamicSharedMemorySize, FLASH_SMEM);

    // splits: x, Wqkv, Wout -> fp16 single
    split_all_kernel<<<(XN4 + WQN4 + WON4 + 255) / 256, 256>>>(
        x, Wqkv, Wout, (__half*)xh, (__half*)wqh, (__half*)woh);

    // 1) QKV projection (fp16 1-pass, 128x128 tile) -> fp16 Q,K,V singles
    gemm_f16<<<dim3(QKV_N / 128, Mv / 128), 256, 2 * STG_B>>>(
        (const __half*)xh, (const __half*)wqh, bqkv, nullptr, 0);

    // 2) causal flash attention (fp16 single-pass S and PV)
    flash_mma<<<dim3(Tv / 128, Bv * Hv), 256, FLASH_SMEM>>>();

    // 3) output projection (fp16 1-pass, 128x128 tile)
    gemm_f16<<<dim3(Dv / 128, Mv / 128), 256, 2 * STG_B>>>(
        (const __half*)ah, (const __half*)woh, bout, out, 1);
}